// round 1
// baseline (speedup 1.0000x reference)
#include <cuda_runtime.h>
#include <math.h>

// ---------------------------------------------------------------------------
// Problem constants
// ---------------------------------------------------------------------------
namespace {
constexpr int HID     = 2048;
constexpr int QK_NOPE = 128;
constexpr int QK_ROPE = 64;
constexpr int QK_HEAD = QK_NOPE + QK_ROPE;   // 192
constexpr int Q_LR    = 768;
constexpr int KV_LR   = 512;
constexpr int NH      = 16;
constexpr int V_DIM   = 128;
constexpr int Bb      = 2;
constexpr int Ss      = 4096;
constexpr int Mrows   = Bb * Ss;             // 8192
constexpr int QD      = NH * QK_HEAD;        // 3072
constexpr int KVD     = NH * (QK_NOPE + V_DIM); // 4096
constexpr int KVC_D   = KV_LR + QK_ROPE;     // 576
constexpr int OUT_D   = QK_HEAD + QK_HEAD + V_DIM; // 512
}

// ---------------------------------------------------------------------------
// Device scratch (no cudaMalloc allowed)
// ---------------------------------------------------------------------------
__device__ float g_qc [Mrows * Q_LR];   //  25 MB
__device__ float g_q  [Mrows * QD];     // 100 MB
__device__ float g_kvc[Mrows * KVC_D];  //  19 MB
__device__ float g_kv [Mrows * KVD];    // 134 MB

// ---------------------------------------------------------------------------
// Tiled fp32 GEMM:  C[M,N] = A[M,K] * B[N,K]^T + bias   (both K-major, "NT")
// 128x128 block tile, BK=16, 256 threads, 8x8 micro-tile per thread.
// M is always a multiple of 128; N may not be (576) -> guard N only.
// ---------------------------------------------------------------------------
#define GBM 128
#define GBN 128
#define GBK 16

__global__ void __launch_bounds__(256, 2) gemm_nt_bias(
    const float* __restrict__ A, int lda,
    const float* __restrict__ Bm, int ldb,
    const float* __restrict__ bias,
    float* __restrict__ C, int ldc,
    int N, int K)
{
    __shared__ float As[GBK][GBM + 4];
    __shared__ float Bs[GBK][GBN + 4];

    const int tid = threadIdx.x;
    const int tx  = tid & 15;          // 0..15 -> N direction
    const int ty  = tid >> 4;          // 0..15 -> M direction
    const int bm  = blockIdx.y * GBM;
    const int bn  = blockIdx.x * GBN;

    float acc[8][8];
#pragma unroll
    for (int i = 0; i < 8; i++)
#pragma unroll
        for (int j = 0; j < 8; j++) acc[i][j] = 0.f;

    for (int k0 = 0; k0 < K; k0 += GBK) {
        // Load A tile: 128 rows x 16 k, coalesced along k.
#pragma unroll
        for (int i = 0; i < 8; i++) {
            int idx = i * 256 + tid;
            int r = idx >> 4, kk = idx & 15;
            As[kk][r] = A[(size_t)(bm + r) * lda + (k0 + kk)];
        }
        // Load B tile (rows are output columns): guard n < N.
#pragma unroll
        for (int i = 0; i < 8; i++) {
            int idx = i * 256 + tid;
            int r = idx >> 4, kk = idx & 15;
            int n = bn + r;
            Bs[kk][r] = (n < N) ? Bm[(size_t)n * ldb + (k0 + kk)] : 0.f;
        }
        __syncthreads();

#pragma unroll
        for (int kk = 0; kk < GBK; kk++) {
            float4 a0 = *(const float4*)&As[kk][ty * 8];
            float4 a1 = *(const float4*)&As[kk][ty * 8 + 4];
            float4 b0 = *(const float4*)&Bs[kk][tx * 8];
            float4 b1 = *(const float4*)&Bs[kk][tx * 8 + 4];
            float a[8] = {a0.x, a0.y, a0.z, a0.w, a1.x, a1.y, a1.z, a1.w};
            float b[8] = {b0.x, b0.y, b0.z, b0.w, b1.x, b1.y, b1.z, b1.w};
#pragma unroll
            for (int i = 0; i < 8; i++)
#pragma unroll
                for (int j = 0; j < 8; j++)
                    acc[i][j] = fmaf(a[i], b[j], acc[i][j]);
        }
        __syncthreads();
    }

    // Store with bias.
#pragma unroll
    for (int i = 0; i < 8; i++) {
        int m = bm + ty * 8 + i;
#pragma unroll
        for (int j = 0; j < 8; j++) {
            int n = bn + tx * 8 + j;
            if (n < N) C[(size_t)m * ldc + n] = acc[i][j] + bias[n];
        }
    }
}

// ---------------------------------------------------------------------------
// LayerNorm over D leading elements of each row (row stride ld), in place.
// One block (256 threads) per row.
// ---------------------------------------------------------------------------
__global__ void __launch_bounds__(256) ln_kernel(
    float* __restrict__ X, int ld, int D,
    const float* __restrict__ gamma, const float* __restrict__ beta)
{
    float* x = X + (size_t)blockIdx.x * ld;
    float s = 0.f, s2 = 0.f;
    for (int i = threadIdx.x; i < D; i += 256) {
        float v = x[i];
        s += v; s2 += v * v;
    }
    __shared__ float shs[8], shs2[8];
#pragma unroll
    for (int o = 16; o > 0; o >>= 1) {
        s  += __shfl_down_sync(0xffffffffu, s,  o);
        s2 += __shfl_down_sync(0xffffffffu, s2, o);
    }
    int w = threadIdx.x >> 5, l = threadIdx.x & 31;
    if (l == 0) { shs[w] = s; shs2[w] = s2; }
    __syncthreads();
    if (w == 0) {
        s  = (l < 8) ? shs[l]  : 0.f;
        s2 = (l < 8) ? shs2[l] : 0.f;
#pragma unroll
        for (int o = 4; o > 0; o >>= 1) {
            s  += __shfl_down_sync(0xffffffffu, s,  o);
            s2 += __shfl_down_sync(0xffffffffu, s2, o);
        }
        if (l == 0) { shs[0] = s; shs2[0] = s2; }
    }
    __syncthreads();
    float mu  = shs[0] / D;
    float var = shs2[0] / D - mu * mu;
    float inv = rsqrtf(var + 1e-5f);
    for (int i = threadIdx.x; i < D; i += 256)
        x[i] = (x[i] - mu) * inv * gamma[i] + beta[i];
}

// ---------------------------------------------------------------------------
// Output assembly + RoPE.
// out shape (B, H, S, 512):
//   [0,128)   q_nope    from g_q[row, h*192 + c]
//   [128,192) rope(q_rope) from g_q[row, h*192+128 + d]
//   [192,320) k_nope    from g_kv[row, h*256 + d]
//   [320,384) rope(k_rope) from g_kvc[row, 512 + d]   (head-independent)
//   [384,512) v         from g_kv[row, h*256+128 + d]
// One block per (b,h,s), 512 threads (one per output element).
// ---------------------------------------------------------------------------
__global__ void __launch_bounds__(512) assemble_kernel(
    const float* __restrict__ q,
    const float* __restrict__ kv,
    const float* __restrict__ kvc,
    float* __restrict__ out)
{
    const int bid = blockIdx.x;                 // (b*NH + h)*S + s
    const int s   = bid & (Ss - 1);
    const int h   = (bid >> 12) & (NH - 1);     // Ss = 4096 = 2^12
    const int b   = bid >> 16;                  // NH*Ss = 2^16
    const int row = b * Ss + s;
    const int c   = threadIdx.x;

    float val;
    if (c < QK_NOPE) {
        val = q[(size_t)row * QD + h * QK_HEAD + c];
    } else if (c < QK_HEAD) {
        int d  = c - QK_NOPE;
        int dd = d & 31;
        float inv_freq = 1.f / powf(10000.f, (float)dd * (1.f / 32.f));
        float ang = (float)s * inv_freq;
        float sn, cs;
        sincosf(ang, &sn, &cs);
        const float* base = q + (size_t)row * QD + h * QK_HEAD + QK_NOPE;
        float xv = base[d];
        float ro = (d < 32) ? -base[d + 32] : base[d - 32];
        val = xv * cs + ro * sn;
    } else if (c < QK_HEAD + QK_NOPE) {
        int d = c - QK_HEAD;
        val = kv[(size_t)row * KVD + h * (QK_NOPE + V_DIM) + d];
    } else if (c < 2 * QK_HEAD) {
        int d  = c - (QK_HEAD + QK_NOPE);
        int dd = d & 31;
        float inv_freq = 1.f / powf(10000.f, (float)dd * (1.f / 32.f));
        float ang = (float)s * inv_freq;
        float sn, cs;
        sincosf(ang, &sn, &cs);
        const float* base = kvc + (size_t)row * KVC_D + KV_LR;
        float xv = base[d];
        float ro = (d < 32) ? -base[d + 32] : base[d - 32];
        val = xv * cs + ro * sn;
    } else {
        int d = c - 2 * QK_HEAD;
        val = kv[(size_t)row * KVD + h * (QK_NOPE + V_DIM) + QK_NOPE + d];
    }
    out[(size_t)bid * OUT_D + c] = val;
}

// ---------------------------------------------------------------------------
// Launch
// ---------------------------------------------------------------------------
extern "C" void kernel_launch(void* const* d_in, const int* /*in_sizes*/, int /*n_in*/,
                              void* d_out, int /*out_size*/)
{
    const float* hidden   = (const float*)d_in[0];
    const float* w_qa     = (const float*)d_in[1];
    const float* b_qa     = (const float*)d_in[2];
    const float* g_qa_ln  = (const float*)d_in[3];
    const float* b_qa_ln  = (const float*)d_in[4];
    const float* w_qb     = (const float*)d_in[5];
    const float* b_qb     = (const float*)d_in[6];
    const float* w_kva    = (const float*)d_in[7];
    const float* b_kva    = (const float*)d_in[8];
    const float* g_kva_ln = (const float*)d_in[9];
    const float* b_kva_ln = (const float*)d_in[10];
    const float* w_kvb    = (const float*)d_in[11];
    const float* b_kvb    = (const float*)d_in[12];
    float* out = (float*)d_out;

    float *qc, *q, *kvc, *kv;
    cudaGetSymbolAddress((void**)&qc,  g_qc);
    cudaGetSymbolAddress((void**)&q,   g_q);
    cudaGetSymbolAddress((void**)&kvc, g_kvc);
    cudaGetSymbolAddress((void**)&kv,  g_kv);

    const dim3 blk(256);
    const int mblocks = Mrows / GBM;   // 64

    // q_c = hidden @ w_qa^T + b_qa  (8192 x 768, K=2048)
    gemm_nt_bias<<<dim3(Q_LR / GBN, mblocks), blk>>>(
        hidden, HID, w_qa, HID, b_qa, qc, Q_LR, Q_LR, HID);

    // LN(q_c)
    ln_kernel<<<Mrows, blk>>>(qc, Q_LR, Q_LR, g_qa_ln, b_qa_ln);

    // q = q_c @ w_qb^T + b_qb  (8192 x 3072, K=768)
    gemm_nt_bias<<<dim3(QD / GBN, mblocks), blk>>>(
        qc, Q_LR, w_qb, Q_LR, b_qb, q, QD, QD, Q_LR);

    // kv_c = hidden @ w_kva^T + b_kva  (8192 x 576, K=2048)
    gemm_nt_bias<<<dim3((KVC_D + GBN - 1) / GBN, mblocks), blk>>>(
        hidden, HID, w_kva, HID, b_kva, kvc, KVC_D, KVC_D, HID);

    // LN(kv_c[:, :512]) in place, rope tail untouched
    ln_kernel<<<Mrows, blk>>>(kvc, KVC_D, KV_LR, g_kva_ln, b_kva_ln);

    // kv = kv_c[:, :512] @ w_kvb^T + b_kvb  (8192 x 4096, K=512)
    gemm_nt_bias<<<dim3(KVD / GBN, mblocks), blk>>>(
        kvc, KVC_D, w_kvb, KV_LR, b_kvb, kv, KVD, KVD, KV_LR);

    // assemble + RoPE + transpose into (B, H, S, 512)
    assemble_kernel<<<Bb * NH * Ss, 512>>>(q, kv, kvc, out);
}

// round 4
// speedup vs baseline: 2.7896x; 2.7896x over previous
#include <cuda_runtime.h>
#include <cstdint>
#include <math.h>

// ---------------------------------------------------------------------------
// Problem constants
// ---------------------------------------------------------------------------
namespace {
constexpr int HID     = 2048;
constexpr int QK_NOPE = 128;
constexpr int QK_ROPE = 64;
constexpr int QK_HEAD = QK_NOPE + QK_ROPE;        // 192
constexpr int Q_LR    = 768;
constexpr int KV_LR   = 512;
constexpr int NH      = 16;
constexpr int V_DIM   = 128;
constexpr int Bb      = 2;
constexpr int Ss      = 4096;
constexpr int Mrows   = Bb * Ss;                  // 8192
constexpr int QD      = NH * QK_HEAD;             // 3072
constexpr int KVD     = NH * (QK_NOPE + V_DIM);   // 4096
constexpr int KVC_D   = KV_LR + QK_ROPE;          // 576
constexpr int OUT_D   = 512;
}

// ---------------------------------------------------------------------------
// Device scratch (no cudaMalloc allowed)
// ---------------------------------------------------------------------------
__device__ float g_qc  [Mrows * Q_LR];
__device__ float g_q   [Mrows * QD];
__device__ float g_kvc [Mrows * KVC_D];
__device__ float g_kv  [Mrows * KVD];
__device__ float g_hid [Mrows * HID];        // tf32-rounded hidden
__device__ float g_wqa [Q_LR * HID];
__device__ float g_wqb [QD * Q_LR];
__device__ float g_wkva[KVC_D * HID];
__device__ float g_wkvb[KVD * KV_LR];

// ---------------------------------------------------------------------------
// Helpers
// ---------------------------------------------------------------------------
__device__ __forceinline__ uint32_t smem_u32(const void* p) {
    uint32_t a;
    asm("{ .reg .u64 t; cvta.to.shared.u64 t, %1; cvt.u32.u64 %0, t; }"
        : "=r"(a) : "l"(p));
    return a;
}

__device__ __forceinline__ float tf32_rna(float x) {
    uint32_t u;
    asm("cvt.rna.tf32.f32 %0, %1;" : "=r"(u) : "f"(x));
    return __uint_as_float(u);
}

__device__ __forceinline__ void cp_async16(uint32_t dst, const void* src, bool valid) {
    int sz = valid ? 16 : 0;
    asm volatile("cp.async.ca.shared.global [%0], [%1], 16, %2;"
                 :: "r"(dst), "l"(src), "r"(sz) : "memory");
}
__device__ __forceinline__ void cp_commit() {
    asm volatile("cp.async.commit_group;" ::: "memory");
}
template <int N>
__device__ __forceinline__ void cp_wait() {
    asm volatile("cp.async.wait_group %0;" :: "n"(N) : "memory");
}

// m16n8k8 tf32 MMA (portable PTX, HMMA path — tcgen05 not available at the
// harness's PTX target sm_103)
__device__ __forceinline__ void mma8(float* c,
                                     uint32_t a0, uint32_t a1, uint32_t a2, uint32_t a3,
                                     uint32_t b0, uint32_t b1) {
    asm volatile(
        "mma.sync.aligned.m16n8k8.row.col.f32.tf32.tf32.f32 "
        "{%0,%1,%2,%3}, {%4,%5,%6,%7}, {%8,%9}, {%0,%1,%2,%3};"
        : "+f"(c[0]), "+f"(c[1]), "+f"(c[2]), "+f"(c[3])
        : "r"(a0), "r"(a1), "r"(a2), "r"(a3), "r"(b0), "r"(b1));
}

// ---------------------------------------------------------------------------
// GEMM: C[M,N] = A[M,K] * B[N,K]^T + bias   (both operands K-major, tf32-
// rounded fp32 in memory). Block tile 128(M) x 256(N) x 16(K), 256 threads,
// 8 warps (2 M x 4 N), warp tile 64x64, cp.async double buffer.
// ---------------------------------------------------------------------------
namespace {
constexpr int BM = 128;
constexpr int BN = 256;
constexpr int BK = 16;
constexpr int LDS = 20;                               // floats, conflict-free pad
constexpr int A_ST_F = BM * LDS;                      // 2560 floats
constexpr int B_ST_F = BN * LDS;                      // 5120 floats
constexpr int STAGE_F = A_ST_F + B_ST_F;              // 7680 floats
constexpr uint32_t GEMM_SMEM = 2 * STAGE_F * 4;       // 61440 B
}

__global__ void __launch_bounds__(256, 1) gemm_mma_tf32(
    const float* __restrict__ A, int lda,
    const float* __restrict__ B, int ldb,
    const float* __restrict__ bias,
    float* __restrict__ C, int ldc,
    int N, int K)
{
    extern __shared__ float sm[];
    const uint32_t sm_b = smem_u32(sm);

    const int tid  = threadIdx.x;
    const int wid  = tid >> 5;
    const int lane = tid & 31;
    const int wm   = wid & 1;            // 0..1  -> M
    const int wn   = wid >> 1;           // 0..3  -> N
    const int bm   = blockIdx.y * BM;
    const int bn   = blockIdx.x * BN;
    const int m0   = wm * 64;
    const int n0   = wn * 64;
    const int qr   = lane >> 2;          // lane/4 : 0..7
    const int qc   = lane & 3;           // lane%4 : 0..3

    float acc[4][8][4];
#pragma unroll
    for (int i = 0; i < 4; i++)
#pragma unroll
        for (int j = 0; j < 8; j++)
#pragma unroll
            for (int k = 0; k < 4; k++) acc[i][j][k] = 0.f;

    const int T = K / BK;

    auto issue_stage = [&](int t) {
        const int buf = t & 1;
        const uint32_t aBase = sm_b + (uint32_t)buf * STAGE_F * 4;
        const uint32_t bBase = aBase + A_ST_F * 4;
        const int k0 = t * BK;
        // A: 128 rows x 16 floats = 512 float4, 2 per thread
#pragma unroll
        for (int j = 0; j < 2; ++j) {
            int i = j * 256 + tid;
            int r = i >> 2, c4 = i & 3;
            cp_async16(aBase + (uint32_t)(r * LDS + c4 * 4) * 4,
                       A + (size_t)(bm + r) * lda + k0 + c4 * 4, true);
        }
        // B: 256 rows x 16 floats = 1024 float4, 4 per thread (guard n<N)
#pragma unroll
        for (int j = 0; j < 4; ++j) {
            int i = j * 256 + tid;
            int r = i >> 2, c4 = i & 3;
            int n = bn + r;
            cp_async16(bBase + (uint32_t)(r * LDS + c4 * 4) * 4,
                       B + (size_t)(n < N ? n : 0) * ldb + k0 + c4 * 4, n < N);
        }
        cp_commit();
    };

    issue_stage(0);

    for (int t = 0; t < T; ++t) {
        const bool more = (t + 1 < T);
        if (more) issue_stage(t + 1);
        if (more) cp_wait<1>(); else cp_wait<0>();
        __syncthreads();

        const float* As = sm + (t & 1) * STAGE_F;
        const float* Bs = As + A_ST_F;

#pragma unroll
        for (int kk = 0; kk < 2; ++kk) {
            const int kb = kk * 8;
            uint32_t a[4][4];
#pragma unroll
            for (int mf = 0; mf < 4; ++mf) {
                const float* ap = As + (m0 + mf * 16 + qr) * LDS + kb + qc;
                a[mf][0] = __float_as_uint(ap[0]);
                a[mf][1] = __float_as_uint(ap[8 * LDS]);
                a[mf][2] = __float_as_uint(ap[4]);
                a[mf][3] = __float_as_uint(ap[8 * LDS + 4]);
            }
#pragma unroll
            for (int nf = 0; nf < 8; ++nf) {
                const float* bp = Bs + (n0 + nf * 8 + qr) * LDS + kb + qc;
                uint32_t b0 = __float_as_uint(bp[0]);
                uint32_t b1 = __float_as_uint(bp[4]);
#pragma unroll
                for (int mf = 0; mf < 4; ++mf)
                    mma8(acc[mf][nf], a[mf][0], a[mf][1], a[mf][2], a[mf][3], b0, b1);
            }
        }
        __syncthreads();
    }

    // ---- epilogue: bias + float2 stores (c0/c1 are adjacent columns) ----
#pragma unroll
    for (int nf = 0; nf < 8; ++nf) {
        int col = bn + n0 + nf * 8 + qc * 2;
        if (col >= N) continue;
        float2 bv = *(const float2*)(bias + col);
#pragma unroll
        for (int mf = 0; mf < 4; ++mf) {
            int r = bm + m0 + mf * 16 + qr;
            float2 v0 = make_float2(acc[mf][nf][0] + bv.x, acc[mf][nf][1] + bv.y);
            float2 v1 = make_float2(acc[mf][nf][2] + bv.x, acc[mf][nf][3] + bv.y);
            *(float2*)(C + (size_t)r * ldc + col)       = v0;
            *(float2*)(C + (size_t)(r + 8) * ldc + col) = v1;
        }
    }
}

// ---------------------------------------------------------------------------
// Elementwise tf32 round pass (memory-bound)
// ---------------------------------------------------------------------------
__global__ void __launch_bounds__(256) round_tf32_kernel(
    const float4* __restrict__ in, float4* __restrict__ out, int n4)
{
    int i = blockIdx.x * blockDim.x + threadIdx.x;
    if (i < n4) {
        float4 v = in[i];
        float4 o;
        o.x = tf32_rna(v.x); o.y = tf32_rna(v.y);
        o.z = tf32_rna(v.z); o.w = tf32_rna(v.w);
        out[i] = o;
    }
}

// ---------------------------------------------------------------------------
// LayerNorm over D leading elements of each row (stride ld), in place.
// Output rounded to tf32 (only consumed by tf32 MMAs).
// ---------------------------------------------------------------------------
__global__ void __launch_bounds__(256) ln_kernel(
    float* __restrict__ X, int ld, int D,
    const float* __restrict__ gamma, const float* __restrict__ beta)
{
    float* x = X + (size_t)blockIdx.x * ld;
    float s = 0.f, s2 = 0.f;
    for (int i = threadIdx.x; i < D; i += 256) {
        float v = x[i];
        s += v; s2 += v * v;
    }
    __shared__ float shs[8], shs2[8];
#pragma unroll
    for (int o = 16; o > 0; o >>= 1) {
        s  += __shfl_down_sync(0xffffffffu, s,  o);
        s2 += __shfl_down_sync(0xffffffffu, s2, o);
    }
    int w = threadIdx.x >> 5, l = threadIdx.x & 31;
    if (l == 0) { shs[w] = s; shs2[w] = s2; }
    __syncthreads();
    if (w == 0) {
        s  = (l < 8) ? shs[l]  : 0.f;
        s2 = (l < 8) ? shs2[l] : 0.f;
#pragma unroll
        for (int o = 4; o > 0; o >>= 1) {
            s  += __shfl_down_sync(0xffffffffu, s,  o);
            s2 += __shfl_down_sync(0xffffffffu, s2, o);
        }
        if (l == 0) { shs[0] = s; shs2[0] = s2; }
    }
    __syncthreads();
    float mu  = shs[0] / D;
    float var = shs2[0] / D - mu * mu;
    float inv = rsqrtf(var + 1e-5f);
    for (int i = threadIdx.x; i < D; i += 256)
        x[i] = tf32_rna((x[i] - mu) * inv * gamma[i] + beta[i]);
}

// ---------------------------------------------------------------------------
// Output assembly + RoPE into (B, H, S, 512)
// ---------------------------------------------------------------------------
__global__ void __launch_bounds__(512) assemble_kernel(
    const float* __restrict__ q,
    const float* __restrict__ kv,
    const float* __restrict__ kvc,
    float* __restrict__ out)
{
    const int bid = blockIdx.x;
    const int s   = bid & (Ss - 1);
    const int h   = (bid >> 12) & (NH - 1);
    const int b   = bid >> 16;
    const int row = b * Ss + s;
    const int c   = threadIdx.x;

    float val;
    if (c < QK_NOPE) {
        val = q[(size_t)row * QD + h * QK_HEAD + c];
    } else if (c < QK_HEAD) {
        int d  = c - QK_NOPE;
        int dd = d & 31;
        float inv_freq = 1.f / powf(10000.f, (float)dd * (1.f / 32.f));
        float ang = (float)s * inv_freq;
        float sn, cs;
        sincosf(ang, &sn, &cs);
        const float* base = q + (size_t)row * QD + h * QK_HEAD + QK_NOPE;
        float xv = base[d];
        float ro = (d < 32) ? -base[d + 32] : base[d - 32];
        val = xv * cs + ro * sn;
    } else if (c < QK_HEAD + QK_NOPE) {
        int d = c - QK_HEAD;
        val = kv[(size_t)row * KVD + h * (QK_NOPE + V_DIM) + d];
    } else if (c < 2 * QK_HEAD) {
        int d  = c - (QK_HEAD + QK_NOPE);
        int dd = d & 31;
        float inv_freq = 1.f / powf(10000.f, (float)dd * (1.f / 32.f));
        float ang = (float)s * inv_freq;
        float sn, cs;
        sincosf(ang, &sn, &cs);
        const float* base = kvc + (size_t)row * KVC_D + KV_LR;
        float xv = base[d];
        float ro = (d < 32) ? -base[d + 32] : base[d - 32];
        val = xv * cs + ro * sn;
    } else {
        int d = c - 2 * QK_HEAD;
        val = kv[(size_t)row * KVD + h * (QK_NOPE + V_DIM) + QK_NOPE + d];
    }
    out[(size_t)bid * OUT_D + c] = val;
}

// ---------------------------------------------------------------------------
// Launch
// ---------------------------------------------------------------------------
extern "C" void kernel_launch(void* const* d_in, const int* /*in_sizes*/, int /*n_in*/,
                              void* d_out, int /*out_size*/)
{
    const float* hidden   = (const float*)d_in[0];
    const float* w_qa     = (const float*)d_in[1];
    const float* b_qa     = (const float*)d_in[2];
    const float* g_qa_ln  = (const float*)d_in[3];
    const float* b_qa_ln  = (const float*)d_in[4];
    const float* w_qb     = (const float*)d_in[5];
    const float* b_qb     = (const float*)d_in[6];
    const float* w_kva    = (const float*)d_in[7];
    const float* b_kva    = (const float*)d_in[8];
    const float* g_kva_ln = (const float*)d_in[9];
    const float* b_kva_ln = (const float*)d_in[10];
    const float* w_kvb    = (const float*)d_in[11];
    const float* b_kvb    = (const float*)d_in[12];
    float* out = (float*)d_out;

    float *qc, *q, *kvc, *kv, *hid, *wqa, *wqb, *wkva, *wkvb;
    cudaGetSymbolAddress((void**)&qc,   g_qc);
    cudaGetSymbolAddress((void**)&q,    g_q);
    cudaGetSymbolAddress((void**)&kvc,  g_kvc);
    cudaGetSymbolAddress((void**)&kv,   g_kv);
    cudaGetSymbolAddress((void**)&hid,  g_hid);
    cudaGetSymbolAddress((void**)&wqa,  g_wqa);
    cudaGetSymbolAddress((void**)&wqb,  g_wqb);
    cudaGetSymbolAddress((void**)&wkva, g_wkva);
    cudaGetSymbolAddress((void**)&wkvb, g_wkvb);

    cudaFuncSetAttribute(gemm_mma_tf32,
                         cudaFuncAttributeMaxDynamicSharedMemorySize, GEMM_SMEM);

    auto roundK = [&](const float* src, float* dst, int n) {
        int n4 = n / 4;
        round_tf32_kernel<<<(n4 + 255) / 256, 256>>>(
            (const float4*)src, (float4*)dst, n4);
    };

    // tf32-round all MMA inputs (HW mma truncates; RNA pre-round removes bias)
    roundK(hidden, hid,  Mrows * HID);
    roundK(w_qa,   wqa,  Q_LR * HID);
    roundK(w_qb,   wqb,  QD * Q_LR);
    roundK(w_kva,  wkva, KVC_D * HID);
    roundK(w_kvb,  wkvb, KVD * KV_LR);

    const int mb = Mrows / BM;   // 64

    // q_c = hidden @ w_qa^T + b_qa   (8192 x 768, K=2048)
    gemm_mma_tf32<<<dim3((Q_LR + BN - 1) / BN, mb), 256, GEMM_SMEM>>>(
        hid, HID, wqa, HID, b_qa, qc, Q_LR, Q_LR, HID);

    ln_kernel<<<Mrows, 256>>>(qc, Q_LR, Q_LR, g_qa_ln, b_qa_ln);

    // q = LN(q_c) @ w_qb^T + b_qb   (8192 x 3072, K=768)
    gemm_mma_tf32<<<dim3((QD + BN - 1) / BN, mb), 256, GEMM_SMEM>>>(
        qc, Q_LR, wqb, Q_LR, b_qb, q, QD, QD, Q_LR);

    // kv_c = hidden @ w_kva^T + b_kva   (8192 x 576, K=2048)
    gemm_mma_tf32<<<dim3((KVC_D + BN - 1) / BN, mb), 256, GEMM_SMEM>>>(
        hid, HID, wkva, HID, b_kva, kvc, KVC_D, KVC_D, HID);

    ln_kernel<<<Mrows, 256>>>(kvc, KVC_D, KV_LR, g_kva_ln, b_kva_ln);

    // kv = LN(kv_c) @ w_kvb^T + b_kvb   (8192 x 4096, K=512)
    gemm_mma_tf32<<<dim3((KVD + BN - 1) / BN, mb), 256, GEMM_SMEM>>>(
        kvc, KVC_D, wkvb, KV_LR, b_kvb, kv, KVD, KVD, KV_LR);

    assemble_kernel<<<Bb * NH * Ss, 512>>>(q, kv, kvc, out);
}

// round 5
// speedup vs baseline: 3.2482x; 1.1644x over previous
#include <cuda_runtime.h>
#include <cstdint>
#include <math.h>

// ---------------------------------------------------------------------------
// Problem constants
// ---------------------------------------------------------------------------
namespace {
constexpr int HID     = 2048;
constexpr int QK_NOPE = 128;
constexpr int QK_ROPE = 64;
constexpr int QK_HEAD = QK_NOPE + QK_ROPE;        // 192
constexpr int Q_LR    = 768;
constexpr int KV_LR   = 512;
constexpr int NH      = 16;
constexpr int V_DIM   = 128;
constexpr int Bb      = 2;
constexpr int Ss      = 4096;
constexpr int Mrows   = Bb * Ss;                  // 8192
constexpr int QD      = NH * QK_HEAD;             // 3072
constexpr int KVD     = NH * (QK_NOPE + V_DIM);   // 4096
constexpr int KVC_D   = KV_LR + QK_ROPE;          // 576
constexpr int OUT_D   = 512;
}

// ---------------------------------------------------------------------------
// Device scratch (no cudaMalloc allowed)
// ---------------------------------------------------------------------------
__device__ float g_qc  [Mrows * Q_LR];
__device__ float g_kvc [Mrows * KVC_D];
__device__ float g_hid [Mrows * HID];
__device__ float g_wqa [Q_LR * HID];
__device__ float g_wqb [QD * Q_LR];
__device__ float g_wkva[KVC_D * HID];
__device__ float g_wkvb[KVD * KV_LR];
__device__ float g_cos [Ss * 32];
__device__ float g_sin [Ss * 32];

// ---------------------------------------------------------------------------
// Helpers
// ---------------------------------------------------------------------------
__device__ __forceinline__ uint32_t smem_u32(const void* p) {
    uint32_t a;
    asm("{ .reg .u64 t; cvta.to.shared.u64 t, %1; cvt.u32.u64 %0, t; }"
        : "=r"(a) : "l"(p));
    return a;
}

__device__ __forceinline__ float tf32_rna(float x) {
    uint32_t u;
    asm("cvt.rna.tf32.f32 %0, %1;" : "=r"(u) : "f"(x));
    return __uint_as_float(u);
}

__device__ __forceinline__ void cp_async16(uint32_t dst, const void* src, bool valid) {
    int sz = valid ? 16 : 0;
    asm volatile("cp.async.ca.shared.global [%0], [%1], 16, %2;"
                 :: "r"(dst), "l"(src), "r"(sz) : "memory");
}
__device__ __forceinline__ void cp_commit() {
    asm volatile("cp.async.commit_group;" ::: "memory");
}
template <int N>
__device__ __forceinline__ void cp_wait() {
    asm volatile("cp.async.wait_group %0;" :: "n"(N) : "memory");
}

__device__ __forceinline__ void mma8(float* c,
                                     uint32_t a0, uint32_t a1, uint32_t a2, uint32_t a3,
                                     uint32_t b0, uint32_t b1) {
    asm volatile(
        "mma.sync.aligned.m16n8k8.row.col.f32.tf32.tf32.f32 "
        "{%0,%1,%2,%3}, {%4,%5,%6,%7}, {%8,%9}, {%0,%1,%2,%3};"
        : "+f"(c[0]), "+f"(c[1]), "+f"(c[2]), "+f"(c[3])
        : "r"(a0), "r"(a1), "r"(a2), "r"(a3), "r"(b0), "r"(b1));
}

// ---------------------------------------------------------------------------
// GEMM config: block 128(M) x 256(N) x 16(K), 256 threads, 8 warps (2Mx4N),
// warp tile 64x64, 3-stage cp.async pipeline, 1 __syncthreads per K-iter.
// ---------------------------------------------------------------------------
namespace {
constexpr int BM = 128;
constexpr int BN = 256;
constexpr int BK = 16;
constexpr int NSTAGE = 3;
constexpr int LDSW = 20;                              // pad, conflict-free
constexpr int A_ST_F = BM * LDSW;                     // 2560
constexpr int B_ST_F = BN * LDSW;                     // 5120
constexpr int STAGE_F = A_ST_F + B_ST_F;              // 7680
constexpr uint32_t GEMM_SMEM = NSTAGE * STAGE_F * 4;  // 92160 B
}

enum { EPI_PLAIN = 0, EPI_Q = 1, EPI_KV = 2 };

// C layout:
//  EPI_PLAIN: C[M, ldc] row-major, bias add, guard n < N.
//  EPI_Q:     out (B,H,S,512); cols are q = H x 192 (nope 0..127 | rope 128..191),
//             RoPE applied in-register.  N = 3072, no guard.
//  EPI_KV:    out (B,H,S,512); cols are kv = H x 256 -> knope at 192+, v at 384+.
__global__ void __launch_bounds__(256, 1)
gemm_mma_tf32_epi(const float* __restrict__ A, int lda,
                  const float* __restrict__ B, int ldb,
                  const float* __restrict__ bias,
                  float* __restrict__ C, int ldc,
                  int N, int K, int MODE)
{
    extern __shared__ float sm[];
    const uint32_t sm_b = smem_u32(sm);

    const int tid  = threadIdx.x;
    const int wid  = tid >> 5;
    const int lane = tid & 31;
    const int wm   = wid & 1;
    const int wn   = wid >> 1;
    const int bm   = blockIdx.y * BM;
    const int bn   = blockIdx.x * BN;
    const int m0   = wm * 64;
    const int n0   = wn * 64;
    const int qr   = lane >> 2;
    const int qc   = lane & 3;

    float acc[4][8][4];
#pragma unroll
    for (int i = 0; i < 4; i++)
#pragma unroll
        for (int j = 0; j < 8; j++)
#pragma unroll
            for (int k = 0; k < 4; k++) acc[i][j][k] = 0.f;

    const int T = K / BK;

    auto issue_stage = [&](int t) {
        const int buf = t % NSTAGE;
        const uint32_t aBase = sm_b + (uint32_t)buf * STAGE_F * 4;
        const uint32_t bBase = aBase + A_ST_F * 4;
        const int k0 = t * BK;
#pragma unroll
        for (int j = 0; j < 2; ++j) {
            int i = j * 256 + tid;
            int r = i >> 2, c4 = i & 3;
            cp_async16(aBase + (uint32_t)(r * LDSW + c4 * 4) * 4,
                       A + (size_t)(bm + r) * lda + k0 + c4 * 4, true);
        }
#pragma unroll
        for (int j = 0; j < 4; ++j) {
            int i = j * 256 + tid;
            int r = i >> 2, c4 = i & 3;
            int n = bn + r;
            cp_async16(bBase + (uint32_t)(r * LDSW + c4 * 4) * 4,
                       B + (size_t)(n < N ? n : 0) * ldb + k0 + c4 * 4, n < N);
        }
        cp_commit();
    };

    // prologue: stages 0 .. NSTAGE-2
#pragma unroll
    for (int i = 0; i < NSTAGE - 1; ++i)
        if (i < T) issue_stage(i);

    for (int t = 0; t < T; ++t) {
        // wait stage t complete (handle drained tail)
        if (t < T - 1) cp_wait<NSTAGE - 2>(); else cp_wait<0>();
        __syncthreads();
        if (t + NSTAGE - 1 < T) issue_stage(t + NSTAGE - 1);

        const float* As = sm + (t % NSTAGE) * STAGE_F;
        const float* Bs = As + A_ST_F;

#pragma unroll
        for (int kk = 0; kk < 2; ++kk) {
            const int kb = kk * 8;
            uint32_t a[4][4];
#pragma unroll
            for (int mf = 0; mf < 4; ++mf) {
                const float* ap = As + (m0 + mf * 16 + qr) * LDSW + kb + qc;
                a[mf][0] = __float_as_uint(ap[0]);
                a[mf][1] = __float_as_uint(ap[8 * LDSW]);
                a[mf][2] = __float_as_uint(ap[4]);
                a[mf][3] = __float_as_uint(ap[8 * LDSW + 4]);
            }
#pragma unroll
            for (int nf = 0; nf < 8; ++nf) {
                const float* bp = Bs + (n0 + nf * 8 + qr) * LDSW + kb + qc;
                uint32_t b0 = __float_as_uint(bp[0]);
                uint32_t b1 = __float_as_uint(bp[4]);
#pragma unroll
                for (int mf = 0; mf < 4; ++mf)
                    mma8(acc[mf][nf], a[mf][0], a[mf][1], a[mf][2], a[mf][3], b0, b1);
            }
        }
    }

    // -----------------------------------------------------------------------
    // Epilogues
    // -----------------------------------------------------------------------
    if (MODE == EPI_PLAIN) {
#pragma unroll
        for (int nf = 0; nf < 8; ++nf) {
            int col = bn + n0 + nf * 8 + qc * 2;
            if (col >= N) continue;
            float2 bv = *(const float2*)(bias + col);
#pragma unroll
            for (int mf = 0; mf < 4; ++mf) {
                int r = bm + m0 + mf * 16 + qr;
                float2 v0 = make_float2(acc[mf][nf][0] + bv.x, acc[mf][nf][1] + bv.y);
                float2 v1 = make_float2(acc[mf][nf][2] + bv.x, acc[mf][nf][3] + bv.y);
                *(float2*)(C + (size_t)r * ldc + col)       = v0;
                *(float2*)(C + (size_t)(r + 8) * ldc + col) = v1;
            }
        }
        return;
    }

    if (MODE == EPI_Q) {
        const int gn0  = bn + n0;           // multiple of 64
        const int h    = gn0 / QK_HEAD;
        const int w0   = gn0 % QK_HEAD;     // 0, 64, 128
        const bool rope = (w0 == 128);

        if (!rope) {
#pragma unroll
            for (int nf = 0; nf < 8; ++nf) {
                int col = gn0 + nf * 8 + qc * 2;
                float2 bv = *(const float2*)(bias + col);
                int oc = w0 + nf * 8 + qc * 2;   // q_nope column 0..127
#pragma unroll
                for (int mf = 0; mf < 4; ++mf) {
#pragma unroll
                    for (int half = 0; half < 2; ++half) {
                        int r = bm + m0 + mf * 16 + qr + half * 8;
                        int b = r >> 12, s = r & (Ss - 1);
                        float* op = C + (((size_t)(b * NH + h) * Ss + s) * OUT_D) + oc;
                        *(float2*)op = make_float2(acc[mf][nf][half * 2]     + bv.x,
                                                   acc[mf][nf][half * 2 + 1] + bv.y);
                    }
                }
            }
        } else {
            // pairs: nf (d in [0,32)) with nf+4 (d+32)
#pragma unroll
            for (int nf = 0; nf < 4; ++nf) {
                int d0  = nf * 8 + qc * 2;               // 0..30, even
                int col1 = gn0 + nf * 8 + qc * 2;        // bias col of d
                int col2 = col1 + 32;                    // bias col of d+32
                float2 bv1 = *(const float2*)(bias + col1);
                float2 bv2 = *(const float2*)(bias + col2);
#pragma unroll
                for (int mf = 0; mf < 4; ++mf) {
#pragma unroll
                    for (int half = 0; half < 2; ++half) {
                        int r = bm + m0 + mf * 16 + qr + half * 8;
                        int b = r >> 12, s = r & (Ss - 1);
                        float ca = g_cos[s * 32 + d0],     sa = g_sin[s * 32 + d0];
                        float cbq = g_cos[s * 32 + d0 + 1], sbq = g_sin[s * 32 + d0 + 1];
                        float x1a = acc[mf][nf][half * 2]         + bv1.x;
                        float x1b = acc[mf][nf][half * 2 + 1]     + bv1.y;
                        float x2a = acc[mf][nf + 4][half * 2]     + bv2.x;
                        float x2b = acc[mf][nf + 4][half * 2 + 1] + bv2.y;
                        float* op = C + (((size_t)(b * NH + h) * Ss + s) * OUT_D);
                        *(float2*)(op + 128 + d0) =
                            make_float2(x1a * ca - x2a * sa, x1b * cbq - x2b * sbq);
                        *(float2*)(op + 160 + d0) =
                            make_float2(x2a * ca + x1a * sa, x2b * cbq + x1b * sbq);
                    }
                }
            }
        }
        return;
    }

    // MODE == EPI_KV : BN == 256 == head width; h = blockIdx.x
    {
        const int h = blockIdx.x;
#pragma unroll
        for (int nf = 0; nf < 8; ++nf) {
            int cin = n0 + nf * 8 + qc * 2;          // 0..255 within head
            int col = bn + cin;
            float2 bv = *(const float2*)(bias + col);
            int oc = (cin < 128) ? (192 + cin) : (384 + (cin - 128));
#pragma unroll
            for (int mf = 0; mf < 4; ++mf) {
#pragma unroll
                for (int half = 0; half < 2; ++half) {
                    int r = bm + m0 + mf * 16 + qr + half * 8;
                    int b = r >> 12, s = r & (Ss - 1);
                    float* op = C + (((size_t)(b * NH + h) * Ss + s) * OUT_D) + oc;
                    *(float2*)op = make_float2(acc[mf][nf][half * 2]     + bv.x,
                                               acc[mf][nf][half * 2 + 1] + bv.y);
                }
            }
        }
    }
}

// ---------------------------------------------------------------------------
// RoPE cos/sin table: [s, dd] for s in [0,4096), dd in [0,32)
// ---------------------------------------------------------------------------
__global__ void __launch_bounds__(256) rope_table_kernel()
{
    int idx = blockIdx.x * 256 + threadIdx.x;       // s*32 + dd
    if (idx >= Ss * 32) return;
    int dd = idx & 31;
    int s  = idx >> 5;
    float inv_freq = powf(10000.f, -(float)dd * (1.f / 32.f));
    float ang = (float)s * inv_freq;
    float sn, cs;
    sincosf(ang, &sn, &cs);
    g_cos[idx] = cs;
    g_sin[idx] = sn;
}

// ---------------------------------------------------------------------------
// k_rope broadcast: rope(kvc[:,512:576]) written to all 16 heads, cols 320..383
// 256 threads = 4 rows per block.
// ---------------------------------------------------------------------------
__global__ void __launch_bounds__(256) krope_kernel(
    const float* __restrict__ kvc, float* __restrict__ out)
{
    int row = blockIdx.x * 4 + (threadIdx.x >> 6);
    int d   = threadIdx.x & 63;
    int dd  = d & 31;
    int b   = row >> 12, s = row & (Ss - 1);
    const float* t = kvc + (size_t)row * KVC_D + KV_LR;
    float x1 = t[dd], x2 = t[dd + 32];
    float c = g_cos[s * 32 + dd], sn = g_sin[s * 32 + dd];
    float val = (d < 32) ? (x1 * c - x2 * sn) : (x2 * c + x1 * sn);
#pragma unroll
    for (int h = 0; h < NH; ++h)
        out[(((size_t)(b * NH + h) * Ss + s) * OUT_D) + 320 + d] = val;
}

// ---------------------------------------------------------------------------
// tf32 round pass
// ---------------------------------------------------------------------------
__global__ void __launch_bounds__(256) round_tf32_kernel(
    const float4* __restrict__ in, float4* __restrict__ out, int n4)
{
    int i = blockIdx.x * blockDim.x + threadIdx.x;
    if (i < n4) {
        float4 v = in[i];
        float4 o;
        o.x = tf32_rna(v.x); o.y = tf32_rna(v.y);
        o.z = tf32_rna(v.z); o.w = tf32_rna(v.w);
        out[i] = o;
    }
}

// ---------------------------------------------------------------------------
// LayerNorm (in place, tf32-rounded output)
// ---------------------------------------------------------------------------
__global__ void __launch_bounds__(256) ln_kernel(
    float* __restrict__ X, int ld, int D,
    const float* __restrict__ gamma, const float* __restrict__ beta)
{
    float* x = X + (size_t)blockIdx.x * ld;
    float s = 0.f, s2 = 0.f;
    for (int i = threadIdx.x; i < D; i += 256) {
        float v = x[i];
        s += v; s2 += v * v;
    }
    __shared__ float shs[8], shs2[8];
#pragma unroll
    for (int o = 16; o > 0; o >>= 1) {
        s  += __shfl_down_sync(0xffffffffu, s,  o);
        s2 += __shfl_down_sync(0xffffffffu, s2, o);
    }
    int w = threadIdx.x >> 5, l = threadIdx.x & 31;
    if (l == 0) { shs[w] = s; shs2[w] = s2; }
    __syncthreads();
    if (w == 0) {
        s  = (l < 8) ? shs[l]  : 0.f;
        s2 = (l < 8) ? shs2[l] : 0.f;
#pragma unroll
        for (int o = 4; o > 0; o >>= 1) {
            s  += __shfl_down_sync(0xffffffffu, s,  o);
            s2 += __shfl_down_sync(0xffffffffu, s2, o);
        }
        if (l == 0) { shs[0] = s; shs2[0] = s2; }
    }
    __syncthreads();
    float mu  = shs[0] / D;
    float var = shs2[0] / D - mu * mu;
    float inv = rsqrtf(var + 1e-5f);
    for (int i = threadIdx.x; i < D; i += 256)
        x[i] = tf32_rna((x[i] - mu) * inv * gamma[i] + beta[i]);
}

// ---------------------------------------------------------------------------
// Launch
// ---------------------------------------------------------------------------
extern "C" void kernel_launch(void* const* d_in, const int* /*in_sizes*/, int /*n_in*/,
                              void* d_out, int /*out_size*/)
{
    const float* hidden   = (const float*)d_in[0];
    const float* w_qa     = (const float*)d_in[1];
    const float* b_qa     = (const float*)d_in[2];
    const float* g_qa_ln  = (const float*)d_in[3];
    const float* b_qa_ln  = (const float*)d_in[4];
    const float* w_qb     = (const float*)d_in[5];
    const float* b_qb     = (const float*)d_in[6];
    const float* w_kva    = (const float*)d_in[7];
    const float* b_kva    = (const float*)d_in[8];
    const float* g_kva_ln = (const float*)d_in[9];
    const float* b_kva_ln = (const float*)d_in[10];
    const float* w_kvb    = (const float*)d_in[11];
    const float* b_kvb    = (const float*)d_in[12];
    float* out = (float*)d_out;

    float *qc, *kvc, *hid, *wqa, *wqb, *wkva, *wkvb;
    cudaGetSymbolAddress((void**)&qc,   g_qc);
    cudaGetSymbolAddress((void**)&kvc,  g_kvc);
    cudaGetSymbolAddress((void**)&hid,  g_hid);
    cudaGetSymbolAddress((void**)&wqa,  g_wqa);
    cudaGetSymbolAddress((void**)&wqb,  g_wqb);
    cudaGetSymbolAddress((void**)&wkva, g_wkva);
    cudaGetSymbolAddress((void**)&wkvb, g_wkvb);

    cudaFuncSetAttribute(gemm_mma_tf32_epi,
                         cudaFuncAttributeMaxDynamicSharedMemorySize, GEMM_SMEM);

    auto roundK = [&](const float* src, float* dst, int n) {
        int n4 = n / 4;
        round_tf32_kernel<<<(n4 + 255) / 256, 256>>>(
            (const float4*)src, (float4*)dst, n4);
    };

    rope_table_kernel<<<(Ss * 32 + 255) / 256, 256>>>();

    roundK(hidden, hid,  Mrows * HID);
    roundK(w_qa,   wqa,  Q_LR * HID);
    roundK(w_qb,   wqb,  QD * Q_LR);
    roundK(w_kva,  wkva, KVC_D * HID);
    roundK(w_kvb,  wkvb, KVD * KV_LR);

    const int mb = Mrows / BM;   // 64

    // q_c = hidden @ w_qa^T + b_qa   (8192 x 768, K=2048)
    gemm_mma_tf32_epi<<<dim3((Q_LR + BN - 1) / BN, mb), 256, GEMM_SMEM>>>(
        hid, HID, wqa, HID, b_qa, qc, Q_LR, Q_LR, HID, EPI_PLAIN);

    ln_kernel<<<Mrows, 256>>>(qc, Q_LR, Q_LR, g_qa_ln, b_qa_ln);

    // kv_c = hidden @ w_kva^T + b_kva   (8192 x 576, K=2048)
    gemm_mma_tf32_epi<<<dim3((KVC_D + BN - 1) / BN, mb), 256, GEMM_SMEM>>>(
        hid, HID, wkva, HID, b_kva, kvc, KVC_D, KVC_D, HID, EPI_PLAIN);

    // k_rope broadcast (needs pre-LN kvc tail; tail untouched by LN)
    krope_kernel<<<Mrows / 4, 256>>>(kvc, out);

    ln_kernel<<<Mrows, 256>>>(kvc, KVC_D, KV_LR, g_kva_ln, b_kva_ln);

    // q = LN(q_c) @ w_qb^T + b_qb -> fused RoPE + scatter into out
    gemm_mma_tf32_epi<<<dim3(QD / BN, mb), 256, GEMM_SMEM>>>(
        qc, Q_LR, wqb, Q_LR, b_qb, out, OUT_D, QD, Q_LR, EPI_Q);

    // kv = LN(kv_c) @ w_kvb^T + b_kvb -> fused scatter into out
    gemm_mma_tf32_epi<<<dim3(KVD / BN, mb), 256, GEMM_SMEM>>>(
        kvc, KVC_D, wkvb, KV_LR, b_kvb, out, OUT_D, KVD, KV_LR, EPI_KV);
}

// round 6
// speedup vs baseline: 5.6424x; 1.7371x over previous
#include <cuda_runtime.h>
#include <cuda_fp16.h>
#include <cstdint>
#include <math.h>

// ---------------------------------------------------------------------------
// Problem constants
// ---------------------------------------------------------------------------
namespace {
constexpr int HID     = 2048;
constexpr int QK_NOPE = 128;
constexpr int QK_ROPE = 64;
constexpr int QK_HEAD = QK_NOPE + QK_ROPE;        // 192
constexpr int Q_LR    = 768;
constexpr int KV_LR   = 512;
constexpr int NH      = 16;
constexpr int V_DIM   = 128;
constexpr int Bb      = 2;
constexpr int Ss      = 4096;
constexpr int Mrows   = Bb * Ss;                  // 8192
constexpr int QD      = NH * QK_HEAD;             // 3072
constexpr int KVD     = NH * (QK_NOPE + V_DIM);   // 4096
constexpr int KVC_D   = KV_LR + QK_ROPE;          // 576
constexpr int OUT_D   = 512;
}

// ---------------------------------------------------------------------------
// Device scratch (no cudaMalloc allowed)
// ---------------------------------------------------------------------------
__device__ float  g_qc  [Mrows * Q_LR];     // fp32 GEMM1 out (LN input)
__device__ float  g_kvc [Mrows * KVC_D];    // fp32 GEMM3 out (LN input + rope tail)
__device__ __half g_qch [Mrows * Q_LR];     // LN(q_c) in half
__device__ __half g_kvch[Mrows * KV_LR];    // LN(kv_c) in half
__device__ __half g_hidh[Mrows * HID];
__device__ __half g_wqah [Q_LR * HID];
__device__ __half g_wqbh [QD * Q_LR];
__device__ __half g_wkvah[KVC_D * HID];
__device__ __half g_wkvbh[KVD * KV_LR];
__device__ float  g_cos [Ss * 32];
__device__ float  g_sin [Ss * 32];

// ---------------------------------------------------------------------------
// Helpers
// ---------------------------------------------------------------------------
__device__ __forceinline__ uint32_t smem_u32(const void* p) {
    uint32_t a;
    asm("{ .reg .u64 t; cvta.to.shared.u64 t, %1; cvt.u32.u64 %0, t; }"
        : "=r"(a) : "l"(p));
    return a;
}

__device__ __forceinline__ void cp_async16(uint32_t dst, const void* src, bool valid) {
    int sz = valid ? 16 : 0;
    asm volatile("cp.async.ca.shared.global [%0], [%1], 16, %2;"
                 :: "r"(dst), "l"(src), "r"(sz) : "memory");
}
__device__ __forceinline__ void cp_commit() {
    asm volatile("cp.async.commit_group;" ::: "memory");
}
template <int N>
__device__ __forceinline__ void cp_wait() {
    asm volatile("cp.async.wait_group %0;" :: "n"(N) : "memory");
}

// fp16 MMA m16n8k16, fp32 accumulate (portable PTX; tcgen05 unavailable at
// the harness's sm_103 PTX target)
__device__ __forceinline__ void mma16(float* c,
                                      uint32_t a0, uint32_t a1, uint32_t a2, uint32_t a3,
                                      uint32_t b0, uint32_t b1) {
    asm volatile(
        "mma.sync.aligned.m16n8k16.row.col.f32.f16.f16.f32 "
        "{%0,%1,%2,%3}, {%4,%5,%6,%7}, {%8,%9}, {%0,%1,%2,%3};"
        : "+f"(c[0]), "+f"(c[1]), "+f"(c[2]), "+f"(c[3])
        : "r"(a0), "r"(a1), "r"(a2), "r"(a3), "r"(b0), "r"(b1));
}

// ---------------------------------------------------------------------------
// GEMM config: block 128(M) x 256(N) x 32(K) halves, 256 threads, 8 warps
// (2Mx4N), warp tile 64x64, 3-stage cp.async pipeline.
// ---------------------------------------------------------------------------
namespace {
constexpr int BM = 128;
constexpr int BN = 256;
constexpr int BK = 32;                                // halves per K-iter
constexpr int NSTAGE = 3;
constexpr int LDSH = 40;                              // halves/row incl pad
constexpr int A_ST_H = BM * LDSH;                     // 5120 halves
constexpr int B_ST_H = BN * LDSH;                     // 10240 halves
constexpr int STAGE_H = A_ST_H + B_ST_H;              // 15360 halves
constexpr uint32_t GEMM_SMEM = NSTAGE * STAGE_H * 2;  // 92160 B
}

enum { EPI_PLAIN = 0, EPI_Q = 1, EPI_KV = 2 };

__global__ void __launch_bounds__(256, 1)
gemm_mma_f16_epi(const __half* __restrict__ A, int lda,
                 const __half* __restrict__ B, int ldb,
                 const float* __restrict__ bias,
                 float* __restrict__ C, int ldc,
                 int N, int K, int MODE)
{
    extern __shared__ __half smh[];
    const uint32_t sm_b = smem_u32(smh);

    const int tid  = threadIdx.x;
    const int wid  = tid >> 5;
    const int lane = tid & 31;
    const int wm   = wid & 1;
    const int wn   = wid >> 1;
    const int bm   = blockIdx.y * BM;
    const int bn   = blockIdx.x * BN;
    const int m0   = wm * 64;
    const int n0   = wn * 64;
    const int qr   = lane >> 2;
    const int qc   = lane & 3;

    float acc[4][8][4];
#pragma unroll
    for (int i = 0; i < 4; i++)
#pragma unroll
        for (int j = 0; j < 8; j++)
#pragma unroll
            for (int k = 0; k < 4; k++) acc[i][j][k] = 0.f;

    const int T = K / BK;

    auto issue_stage = [&](int t) {
        const int buf = t % NSTAGE;
        const uint32_t aBase = sm_b + (uint32_t)buf * STAGE_H * 2;
        const uint32_t bBase = aBase + A_ST_H * 2;
        const int k0 = t * BK;
        // A: 128 rows x 32 halves = 512 x 16B chunks, 2/thread
#pragma unroll
        for (int j = 0; j < 2; ++j) {
            int i = j * 256 + tid;
            int r = i >> 2, c8 = i & 3;
            cp_async16(aBase + (uint32_t)(r * LDSH * 2 + c8 * 16),
                       A + (size_t)(bm + r) * lda + k0 + c8 * 8, true);
        }
        // B: 256 rows x 32 halves = 1024 x 16B chunks, 4/thread (guard n<N)
#pragma unroll
        for (int j = 0; j < 4; ++j) {
            int i = j * 256 + tid;
            int r = i >> 2, c8 = i & 3;
            int n = bn + r;
            cp_async16(bBase + (uint32_t)(r * LDSH * 2 + c8 * 16),
                       B + (size_t)(n < N ? n : 0) * ldb + k0 + c8 * 8, n < N);
        }
        cp_commit();
    };

#pragma unroll
    for (int i = 0; i < NSTAGE - 1; ++i)
        if (i < T) issue_stage(i);

    for (int t = 0; t < T; ++t) {
        if (t < T - 1) cp_wait<NSTAGE - 2>(); else cp_wait<0>();
        __syncthreads();
        if (t + NSTAGE - 1 < T) issue_stage(t + NSTAGE - 1);

        const __half* As = smh + (t % NSTAGE) * STAGE_H;
        const __half* Bs = As + A_ST_H;

#pragma unroll
        for (int kk = 0; kk < 2; ++kk) {
            const int kb = kk * 16;
            uint32_t a[4][4];
#pragma unroll
            for (int mf = 0; mf < 4; ++mf) {
                const __half* lo = As + (m0 + mf * 16 + qr) * LDSH + kb + qc * 2;
                const __half* hi = lo + 8 * LDSH;
                a[mf][0] = *(const uint32_t*)lo;
                a[mf][1] = *(const uint32_t*)hi;
                a[mf][2] = *(const uint32_t*)(lo + 8);
                a[mf][3] = *(const uint32_t*)(hi + 8);
            }
#pragma unroll
            for (int nf = 0; nf < 8; ++nf) {
                const __half* bp = Bs + (n0 + nf * 8 + qr) * LDSH + kb + qc * 2;
                uint32_t b0 = *(const uint32_t*)bp;
                uint32_t b1 = *(const uint32_t*)(bp + 8);
#pragma unroll
                for (int mf = 0; mf < 4; ++mf)
                    mma16(acc[mf][nf], a[mf][0], a[mf][1], a[mf][2], a[mf][3], b0, b1);
            }
        }
    }

    // -----------------------------------------------------------------------
    // Epilogues (accumulator fragment layout identical to k8 variant)
    // -----------------------------------------------------------------------
    if (MODE == EPI_PLAIN) {
#pragma unroll
        for (int nf = 0; nf < 8; ++nf) {
            int col = bn + n0 + nf * 8 + qc * 2;
            if (col >= N) continue;
            float2 bv = *(const float2*)(bias + col);
#pragma unroll
            for (int mf = 0; mf < 4; ++mf) {
                int r = bm + m0 + mf * 16 + qr;
                *(float2*)(C + (size_t)r * ldc + col) =
                    make_float2(acc[mf][nf][0] + bv.x, acc[mf][nf][1] + bv.y);
                *(float2*)(C + (size_t)(r + 8) * ldc + col) =
                    make_float2(acc[mf][nf][2] + bv.x, acc[mf][nf][3] + bv.y);
            }
        }
        return;
    }

    if (MODE == EPI_Q) {
        const int gn0  = bn + n0;           // multiple of 64
        const int h    = gn0 / QK_HEAD;
        const int w0   = gn0 % QK_HEAD;     // 0, 64, 128
        const bool rope = (w0 == 128);

        if (!rope) {
#pragma unroll
            for (int nf = 0; nf < 8; ++nf) {
                int col = gn0 + nf * 8 + qc * 2;
                float2 bv = *(const float2*)(bias + col);
                int oc = w0 + nf * 8 + qc * 2;
#pragma unroll
                for (int mf = 0; mf < 4; ++mf) {
#pragma unroll
                    for (int half = 0; half < 2; ++half) {
                        int r = bm + m0 + mf * 16 + qr + half * 8;
                        int b = r >> 12, s = r & (Ss - 1);
                        float* op = C + (((size_t)(b * NH + h) * Ss + s) * OUT_D) + oc;
                        *(float2*)op = make_float2(acc[mf][nf][half * 2]     + bv.x,
                                                   acc[mf][nf][half * 2 + 1] + bv.y);
                    }
                }
            }
        } else {
#pragma unroll
            for (int nf = 0; nf < 4; ++nf) {
                int d0  = nf * 8 + qc * 2;
                int col1 = gn0 + nf * 8 + qc * 2;
                int col2 = col1 + 32;
                float2 bv1 = *(const float2*)(bias + col1);
                float2 bv2 = *(const float2*)(bias + col2);
#pragma unroll
                for (int mf = 0; mf < 4; ++mf) {
#pragma unroll
                    for (int half = 0; half < 2; ++half) {
                        int r = bm + m0 + mf * 16 + qr + half * 8;
                        int b = r >> 12, s = r & (Ss - 1);
                        float ca = g_cos[s * 32 + d0],      sa = g_sin[s * 32 + d0];
                        float cbq = g_cos[s * 32 + d0 + 1], sbq = g_sin[s * 32 + d0 + 1];
                        float x1a = acc[mf][nf][half * 2]         + bv1.x;
                        float x1b = acc[mf][nf][half * 2 + 1]     + bv1.y;
                        float x2a = acc[mf][nf + 4][half * 2]     + bv2.x;
                        float x2b = acc[mf][nf + 4][half * 2 + 1] + bv2.y;
                        float* op = C + (((size_t)(b * NH + h) * Ss + s) * OUT_D);
                        *(float2*)(op + 128 + d0) =
                            make_float2(x1a * ca - x2a * sa, x1b * cbq - x2b * sbq);
                        *(float2*)(op + 160 + d0) =
                            make_float2(x2a * ca + x1a * sa, x2b * cbq + x1b * sbq);
                    }
                }
            }
        }
        return;
    }

    // MODE == EPI_KV : BN == 256 == head width; h = blockIdx.x
    {
        const int h = blockIdx.x;
#pragma unroll
        for (int nf = 0; nf < 8; ++nf) {
            int cin = n0 + nf * 8 + qc * 2;
            int col = bn + cin;
            float2 bv = *(const float2*)(bias + col);
            int oc = (cin < 128) ? (192 + cin) : (384 + (cin - 128));
#pragma unroll
            for (int mf = 0; mf < 4; ++mf) {
#pragma unroll
                for (int half = 0; half < 2; ++half) {
                    int r = bm + m0 + mf * 16 + qr + half * 8;
                    int b = r >> 12, s = r & (Ss - 1);
                    float* op = C + (((size_t)(b * NH + h) * Ss + s) * OUT_D) + oc;
                    *(float2*)op = make_float2(acc[mf][nf][half * 2]     + bv.x,
                                               acc[mf][nf][half * 2 + 1] + bv.y);
                }
            }
        }
    }
}

// ---------------------------------------------------------------------------
// RoPE cos/sin table
// ---------------------------------------------------------------------------
__global__ void __launch_bounds__(256) rope_table_kernel()
{
    int idx = blockIdx.x * 256 + threadIdx.x;
    if (idx >= Ss * 32) return;
    int dd = idx & 31;
    int s  = idx >> 5;
    float inv_freq = powf(10000.f, -(float)dd * (1.f / 32.f));
    float ang = (float)s * inv_freq;
    float sn, cs;
    sincosf(ang, &sn, &cs);
    g_cos[idx] = cs;
    g_sin[idx] = sn;
}

// ---------------------------------------------------------------------------
// k_rope broadcast: rope(kvc[:,512:576]) to all 16 heads, cols 320..383
// ---------------------------------------------------------------------------
__global__ void __launch_bounds__(256) krope_kernel(
    const float* __restrict__ kvc, float* __restrict__ out)
{
    int row = blockIdx.x * 4 + (threadIdx.x >> 6);
    int d   = threadIdx.x & 63;
    int dd  = d & 31;
    int b   = row >> 12, s = row & (Ss - 1);
    const float* t = kvc + (size_t)row * KVC_D + KV_LR;
    float x1 = t[dd], x2 = t[dd + 32];
    float c = g_cos[s * 32 + dd], sn = g_sin[s * 32 + dd];
    float val = (d < 32) ? (x1 * c - x2 * sn) : (x2 * c + x1 * sn);
#pragma unroll
    for (int h = 0; h < NH; ++h)
        out[(((size_t)(b * NH + h) * Ss + s) * OUT_D) + 320 + d] = val;
}

// ---------------------------------------------------------------------------
// fp32 -> fp16 conversion pass
// ---------------------------------------------------------------------------
__global__ void __launch_bounds__(256) to_half_kernel(
    const float4* __restrict__ in, uint2* __restrict__ out, int n4)
{
    int i = blockIdx.x * blockDim.x + threadIdx.x;
    if (i < n4) {
        float4 v = in[i];
        __half2 h0 = __floats2half2_rn(v.x, v.y);
        __half2 h1 = __floats2half2_rn(v.z, v.w);
        out[i] = make_uint2(*(uint32_t*)&h0, *(uint32_t*)&h1);
    }
}

// ---------------------------------------------------------------------------
// LayerNorm: fp32 input (stride ld_in, D cols), half output (stride ld_out)
// ---------------------------------------------------------------------------
__global__ void __launch_bounds__(256) ln_half_kernel(
    const float* __restrict__ X, int ld_in, int D,
    const float* __restrict__ gamma, const float* __restrict__ beta,
    __half* __restrict__ Y, int ld_out)
{
    const float* x = X + (size_t)blockIdx.x * ld_in;
    __half* y = Y + (size_t)blockIdx.x * ld_out;
    float s = 0.f, s2 = 0.f;
    for (int i = threadIdx.x; i < D; i += 256) {
        float v = x[i];
        s += v; s2 += v * v;
    }
    __shared__ float shs[8], shs2[8];
#pragma unroll
    for (int o = 16; o > 0; o >>= 1) {
        s  += __shfl_down_sync(0xffffffffu, s,  o);
        s2 += __shfl_down_sync(0xffffffffu, s2, o);
    }
    int w = threadIdx.x >> 5, l = threadIdx.x & 31;
    if (l == 0) { shs[w] = s; shs2[w] = s2; }
    __syncthreads();
    if (w == 0) {
        s  = (l < 8) ? shs[l]  : 0.f;
        s2 = (l < 8) ? shs2[l] : 0.f;
#pragma unroll
        for (int o = 4; o > 0; o >>= 1) {
            s  += __shfl_down_sync(0xffffffffu, s,  o);
            s2 += __shfl_down_sync(0xffffffffu, s2, o);
        }
        if (l == 0) { shs[0] = s; shs2[0] = s2; }
    }
    __syncthreads();
    float mu  = shs[0] / D;
    float var = shs2[0] / D - mu * mu;
    float inv = rsqrtf(var + 1e-5f);
    for (int i = threadIdx.x; i < D; i += 256)
        y[i] = __float2half_rn((x[i] - mu) * inv * gamma[i] + beta[i]);
}

// ---------------------------------------------------------------------------
// Launch
// ---------------------------------------------------------------------------
extern "C" void kernel_launch(void* const* d_in, const int* /*in_sizes*/, int /*n_in*/,
                              void* d_out, int /*out_size*/)
{
    const float* hidden   = (const float*)d_in[0];
    const float* w_qa     = (const float*)d_in[1];
    const float* b_qa     = (const float*)d_in[2];
    const float* g_qa_ln  = (const float*)d_in[3];
    const float* b_qa_ln  = (const float*)d_in[4];
    const float* w_qb     = (const float*)d_in[5];
    const float* b_qb     = (const float*)d_in[6];
    const float* w_kva    = (const float*)d_in[7];
    const float* b_kva    = (const float*)d_in[8];
    const float* g_kva_ln = (const float*)d_in[9];
    const float* b_kva_ln = (const float*)d_in[10];
    const float* w_kvb    = (const float*)d_in[11];
    const float* b_kvb    = (const float*)d_in[12];
    float* out = (float*)d_out;

    float  *qc, *kvc;
    __half *qch, *kvch, *hidh, *wqah, *wqbh, *wkvah, *wkvbh;
    cudaGetSymbolAddress((void**)&qc,    g_qc);
    cudaGetSymbolAddress((void**)&kvc,   g_kvc);
    cudaGetSymbolAddress((void**)&qch,   g_qch);
    cudaGetSymbolAddress((void**)&kvch,  g_kvch);
    cudaGetSymbolAddress((void**)&hidh,  g_hidh);
    cudaGetSymbolAddress((void**)&wqah,  g_wqah);
    cudaGetSymbolAddress((void**)&wqbh,  g_wqbh);
    cudaGetSymbolAddress((void**)&wkvah, g_wkvah);
    cudaGetSymbolAddress((void**)&wkvbh, g_wkvbh);

    cudaFuncSetAttribute(gemm_mma_f16_epi,
                         cudaFuncAttributeMaxDynamicSharedMemorySize, GEMM_SMEM);

    auto toHalf = [&](const float* src, __half* dst, int n) {
        int n4 = n / 4;
        to_half_kernel<<<(n4 + 255) / 256, 256>>>(
            (const float4*)src, (uint2*)dst, n4);
    };

    rope_table_kernel<<<(Ss * 32 + 255) / 256, 256>>>();

    toHalf(hidden, hidh,  Mrows * HID);
    toHalf(w_qa,   wqah,  Q_LR * HID);
    toHalf(w_qb,   wqbh,  QD * Q_LR);
    toHalf(w_kva,  wkvah, KVC_D * HID);
    toHalf(w_kvb,  wkvbh, KVD * KV_LR);

    const int mb = Mrows / BM;   // 64

    // q_c = hidden @ w_qa^T + b_qa   (8192 x 768, K=2048)
    gemm_mma_f16_epi<<<dim3((Q_LR + BN - 1) / BN, mb), 256, GEMM_SMEM>>>(
        hidh, HID, wqah, HID, b_qa, qc, Q_LR, Q_LR, HID, EPI_PLAIN);

    ln_half_kernel<<<Mrows, 256>>>(qc, Q_LR, Q_LR, g_qa_ln, b_qa_ln, qch, Q_LR);

    // kv_c = hidden @ w_kva^T + b_kva   (8192 x 576, K=2048)
    gemm_mma_f16_epi<<<dim3((KVC_D + BN - 1) / BN, mb), 256, GEMM_SMEM>>>(
        hidh, HID, wkvah, HID, b_kva, kvc, KVC_D, KVC_D, HID, EPI_PLAIN);

    // k_rope broadcast (pre-LN tail, untouched by LN)
    krope_kernel<<<Mrows / 4, 256>>>(kvc, out);

    ln_half_kernel<<<Mrows, 256>>>(kvc, KVC_D, KV_LR, g_kva_ln, b_kva_ln,
                                   kvch, KV_LR);

    // q = LN(q_c) @ w_qb^T + b_qb -> fused RoPE + scatter
    gemm_mma_f16_epi<<<dim3(QD / BN, mb), 256, GEMM_SMEM>>>(
        qch, Q_LR, wqbh, Q_LR, b_qb, out, OUT_D, QD, Q_LR, EPI_Q);

    // kv = LN(kv_c) @ w_kvb^T + b_kvb -> fused scatter
    gemm_mma_f16_epi<<<dim3(KVD / BN, mb), 256, GEMM_SMEM>>>(
        kvch, KV_LR, wkvbh, KV_LR, b_kvb, out, OUT_D, KVD, KV_LR, EPI_KV);
}

// round 8
// speedup vs baseline: 5.7916x; 1.0264x over previous
#include <cuda_runtime.h>
#include <cuda_fp16.h>
#include <cstdint>
#include <math.h>

// ---------------------------------------------------------------------------
// Problem constants
// ---------------------------------------------------------------------------
namespace {
constexpr int HID     = 2048;
constexpr int QK_NOPE = 128;
constexpr int QK_ROPE = 64;
constexpr int QK_HEAD = QK_NOPE + QK_ROPE;        // 192
constexpr int Q_LR    = 768;
constexpr int KV_LR   = 512;
constexpr int NH      = 16;
constexpr int V_DIM   = 128;
constexpr int Bb      = 2;
constexpr int Ss      = 4096;
constexpr int Mrows   = Bb * Ss;                  // 8192
constexpr int QD      = NH * QK_HEAD;             // 3072
constexpr int KVD     = NH * (QK_NOPE + V_DIM);   // 4096
constexpr int KVC_D   = KV_LR + QK_ROPE;          // 576
constexpr int OUT_D   = 512;
}

// ---------------------------------------------------------------------------
// Device scratch (no cudaMalloc allowed)
// ---------------------------------------------------------------------------
__device__ float  g_qc  [Mrows * Q_LR];
__device__ float  g_kvc [Mrows * KVC_D];
__device__ __half g_qch [Mrows * Q_LR];
__device__ __half g_kvch[Mrows * KV_LR];
__device__ __half g_hidh[Mrows * HID];
__device__ __half g_wqah [Q_LR * HID];
__device__ __half g_wqbh [QD * Q_LR];
__device__ __half g_wkvah[KVC_D * HID];
__device__ __half g_wkvbh[KVD * KV_LR];
__device__ float  g_cos [Ss * 32];
__device__ float  g_sin [Ss * 32];

// ---------------------------------------------------------------------------
// Helpers
// ---------------------------------------------------------------------------
__device__ __forceinline__ uint32_t smem_u32(const void* p) {
    uint32_t a;
    asm("{ .reg .u64 t; cvta.to.shared.u64 t, %1; cvt.u32.u64 %0, t; }"
        : "=r"(a) : "l"(p));
    return a;
}

__device__ __forceinline__ void cp_async16(uint32_t dst, const void* src, bool valid) {
    int sz = valid ? 16 : 0;
    asm volatile("cp.async.ca.shared.global [%0], [%1], 16, %2;"
                 :: "r"(dst), "l"(src), "r"(sz) : "memory");
}
__device__ __forceinline__ void cp_commit() {
    asm volatile("cp.async.commit_group;" ::: "memory");
}
template <int N>
__device__ __forceinline__ void cp_wait() {
    asm volatile("cp.async.wait_group %0;" :: "n"(N) : "memory");
}

__device__ __forceinline__ void ldsm4(uint32_t& r0, uint32_t& r1,
                                      uint32_t& r2, uint32_t& r3, uint32_t addr) {
    asm volatile("ldmatrix.sync.aligned.m8n8.x4.shared.b16 {%0,%1,%2,%3}, [%4];"
                 : "=r"(r0), "=r"(r1), "=r"(r2), "=r"(r3) : "r"(addr));
}

// fp16 MMA m16n8k16, fp32 accumulate
__device__ __forceinline__ void mma16(float* c,
                                      uint32_t a0, uint32_t a1, uint32_t a2, uint32_t a3,
                                      uint32_t b0, uint32_t b1) {
    asm volatile(
        "mma.sync.aligned.m16n8k16.row.col.f32.f16.f16.f32 "
        "{%0,%1,%2,%3}, {%4,%5,%6,%7}, {%8,%9}, {%0,%1,%2,%3};"
        : "+f"(c[0]), "+f"(c[1]), "+f"(c[2]), "+f"(c[3])
        : "r"(a0), "r"(a1), "r"(a2), "r"(a3), "r"(b0), "r"(b1));
}

// ---------------------------------------------------------------------------
// GEMM config: block 128(M) x 256(N) x 32(K) halves, 256 threads, 8 warps
// (2Mx4N), warp tile 64x64, 3-stage cp.async pipeline, ldmatrix fragments.
// ---------------------------------------------------------------------------
namespace {
constexpr int BM = 128;
constexpr int BN = 256;
constexpr int BK = 32;
constexpr int NSTAGE = 3;
constexpr int LDSH = 40;                              // halves/row incl pad
constexpr int A_ST_H = BM * LDSH;
constexpr int B_ST_H = BN * LDSH;
constexpr int STAGE_H = A_ST_H + B_ST_H;              // 15360 halves
constexpr uint32_t GEMM_SMEM = NSTAGE * STAGE_H * 2;  // 92160 B
}

enum { EPI_PLAIN = 0, EPI_Q = 1, EPI_KV = 2 };

__global__ void __launch_bounds__(256, 1)
gemm_mma_f16_epi(const __half* __restrict__ A, int lda,
                 const __half* __restrict__ B, int ldb,
                 const float* __restrict__ bias,
                 float* __restrict__ C, int ldc,
                 int N, int K, int MODE)
{
    extern __shared__ __half smh[];
    const uint32_t sm_b = smem_u32(smh);

    const int tid  = threadIdx.x;
    const int wid  = tid >> 5;
    const int lane = tid & 31;
    const int wm   = wid & 1;
    const int wn   = wid >> 1;
    const int bm   = blockIdx.y * BM;
    const int bn   = blockIdx.x * BN;
    const int m0   = wm * 64;
    const int n0   = wn * 64;
    const int qr   = lane >> 2;
    const int qc   = lane & 3;

    // ldmatrix per-lane address components
    const int aRow  = m0 + (lane & 15);               // + mf*16
    const int aKoff = (lane >> 4) * 8;
    const int bRow  = n0 + ((lane >> 4) & 1) * 8 + (lane & 7);   // + nfp*16
    const int bKoff = ((lane >> 3) & 1) * 8;

    float acc[4][8][4];
#pragma unroll
    for (int i = 0; i < 4; i++)
#pragma unroll
        for (int j = 0; j < 8; j++)
#pragma unroll
            for (int k = 0; k < 4; k++) acc[i][j][k] = 0.f;

    const int T = K / BK;

    auto issue_stage = [&](int t) {
        const int buf = t % NSTAGE;
        const uint32_t aBase = sm_b + (uint32_t)buf * STAGE_H * 2;
        const uint32_t bBase = aBase + A_ST_H * 2;
        const int k0 = t * BK;
#pragma unroll
        for (int j = 0; j < 2; ++j) {
            int i = j * 256 + tid;
            int r = i >> 2, c8 = i & 3;
            cp_async16(aBase + (uint32_t)(r * LDSH * 2 + c8 * 16),
                       A + (size_t)(bm + r) * lda + k0 + c8 * 8, true);
        }
#pragma unroll
        for (int j = 0; j < 4; ++j) {
            int i = j * 256 + tid;
            int r = i >> 2, c8 = i & 3;
            int n = bn + r;
            cp_async16(bBase + (uint32_t)(r * LDSH * 2 + c8 * 16),
                       B + (size_t)(n < N ? n : 0) * ldb + k0 + c8 * 8, n < N);
        }
        cp_commit();
    };

#pragma unroll
    for (int i = 0; i < NSTAGE - 1; ++i)
        if (i < T) issue_stage(i);

    for (int t = 0; t < T; ++t) {
        if (t < T - 1) cp_wait<NSTAGE - 2>(); else cp_wait<0>();
        __syncthreads();
        if (t + NSTAGE - 1 < T) issue_stage(t + NSTAGE - 1);

        const uint32_t As_u = sm_b + (uint32_t)(t % NSTAGE) * STAGE_H * 2;
        const uint32_t Bs_u = As_u + A_ST_H * 2;

#pragma unroll
        for (int kk = 0; kk < 2; ++kk) {
            const int kb = kk * 16;
            uint32_t a[4][4];
#pragma unroll
            for (int mf = 0; mf < 4; ++mf)
                ldsm4(a[mf][0], a[mf][1], a[mf][2], a[mf][3],
                      As_u + (uint32_t)((aRow + mf * 16) * LDSH + kb + aKoff) * 2);
            uint32_t b[8][2];
#pragma unroll
            for (int nfp = 0; nfp < 4; ++nfp)
                ldsm4(b[2 * nfp][0], b[2 * nfp][1], b[2 * nfp + 1][0], b[2 * nfp + 1][1],
                      Bs_u + (uint32_t)((bRow + nfp * 16) * LDSH + kb + bKoff) * 2);
#pragma unroll
            for (int nf = 0; nf < 8; ++nf)
#pragma unroll
                for (int mf = 0; mf < 4; ++mf)
                    mma16(acc[mf][nf], a[mf][0], a[mf][1], a[mf][2], a[mf][3],
                          b[nf][0], b[nf][1]);
        }
    }

    // -----------------------------------------------------------------------
    // Epilogues
    // -----------------------------------------------------------------------
    if (MODE == EPI_PLAIN) {
#pragma unroll
        for (int nf = 0; nf < 8; ++nf) {
            int col = bn + n0 + nf * 8 + qc * 2;
            if (col >= N) continue;
            float2 bv = *(const float2*)(bias + col);
#pragma unroll
            for (int mf = 0; mf < 4; ++mf) {
                int r = bm + m0 + mf * 16 + qr;
                *(float2*)(C + (size_t)r * ldc + col) =
                    make_float2(acc[mf][nf][0] + bv.x, acc[mf][nf][1] + bv.y);
                *(float2*)(C + (size_t)(r + 8) * ldc + col) =
                    make_float2(acc[mf][nf][2] + bv.x, acc[mf][nf][3] + bv.y);
            }
        }
        return;
    }

    if (MODE == EPI_Q) {
        const int gn0  = bn + n0;
        const int h    = gn0 / QK_HEAD;
        const int w0   = gn0 % QK_HEAD;     // 0, 64, 128
        const bool rope = (w0 == 128);

        if (!rope) {
#pragma unroll
            for (int nf = 0; nf < 8; ++nf) {
                int col = gn0 + nf * 8 + qc * 2;
                float2 bv = *(const float2*)(bias + col);
                int oc = w0 + nf * 8 + qc * 2;
#pragma unroll
                for (int mf = 0; mf < 4; ++mf) {
#pragma unroll
                    for (int half = 0; half < 2; ++half) {
                        int r = bm + m0 + mf * 16 + qr + half * 8;
                        int b = r >> 12, s = r & (Ss - 1);
                        float* op = C + (((size_t)(b * NH + h) * Ss + s) * OUT_D) + oc;
                        *(float2*)op = make_float2(acc[mf][nf][half * 2]     + bv.x,
                                                   acc[mf][nf][half * 2 + 1] + bv.y);
                    }
                }
            }
        } else {
#pragma unroll
            for (int nf = 0; nf < 4; ++nf) {
                int d0  = nf * 8 + qc * 2;
                int col1 = gn0 + nf * 8 + qc * 2;
                int col2 = col1 + 32;
                float2 bv1 = *(const float2*)(bias + col1);
                float2 bv2 = *(const float2*)(bias + col2);
#pragma unroll
                for (int mf = 0; mf < 4; ++mf) {
#pragma unroll
                    for (int half = 0; half < 2; ++half) {
                        int r = bm + m0 + mf * 16 + qr + half * 8;
                        int b = r >> 12, s = r & (Ss - 1);
                        float ca = g_cos[s * 32 + d0],      sa = g_sin[s * 32 + d0];
                        float cbq = g_cos[s * 32 + d0 + 1], sbq = g_sin[s * 32 + d0 + 1];
                        float x1a = acc[mf][nf][half * 2]         + bv1.x;
                        float x1b = acc[mf][nf][half * 2 + 1]     + bv1.y;
                        float x2a = acc[mf][nf + 4][half * 2]     + bv2.x;
                        float x2b = acc[mf][nf + 4][half * 2 + 1] + bv2.y;
                        float* op = C + (((size_t)(b * NH + h) * Ss + s) * OUT_D);
                        *(float2*)(op + 128 + d0) =
                            make_float2(x1a * ca - x2a * sa, x1b * cbq - x2b * sbq);
                        *(float2*)(op + 160 + d0) =
                            make_float2(x2a * ca + x1a * sa, x2b * cbq + x1b * sbq);
                    }
                }
            }
        }
        return;
    }

    // MODE == EPI_KV : BN == 256 == head width; h = blockIdx.x
    {
        const int h = blockIdx.x;
#pragma unroll
        for (int nf = 0; nf < 8; ++nf) {
            int cin = n0 + nf * 8 + qc * 2;
            int col = bn + cin;
            float2 bv = *(const float2*)(bias + col);
            int oc = (cin < 128) ? (192 + cin) : (384 + (cin - 128));
#pragma unroll
            for (int mf = 0; mf < 4; ++mf) {
#pragma unroll
                for (int half = 0; half < 2; ++half) {
                    int r = bm + m0 + mf * 16 + qr + half * 8;
                    int b = r >> 12, s = r & (Ss - 1);
                    float* op = C + (((size_t)(b * NH + h) * Ss + s) * OUT_D) + oc;
                    *(float2*)op = make_float2(acc[mf][nf][half * 2]     + bv.x,
                                               acc[mf][nf][half * 2 + 1] + bv.y);
                }
            }
        }
    }
}

// ---------------------------------------------------------------------------
// RoPE cos/sin table
// ---------------------------------------------------------------------------
__global__ void __launch_bounds__(256) rope_table_kernel()
{
    int idx = blockIdx.x * 256 + threadIdx.x;
    if (idx >= Ss * 32) return;
    int dd = idx & 31;
    int s  = idx >> 5;
    float inv_freq = powf(10000.f, -(float)dd * (1.f / 32.f));
    float ang = (float)s * inv_freq;
    float sn, cs;
    sincosf(ang, &sn, &cs);
    g_cos[idx] = cs;
    g_sin[idx] = sn;
}

// ---------------------------------------------------------------------------
// k_rope broadcast: rope(kvc[:,512:576]) to all 16 heads, cols 320..383
// ---------------------------------------------------------------------------
__global__ void __launch_bounds__(256) krope_kernel(
    const float* __restrict__ kvc, float* __restrict__ out)
{
    int row = blockIdx.x * 4 + (threadIdx.x >> 6);
    int d   = threadIdx.x & 63;
    int dd  = d & 31;
    int b   = row >> 12, s = row & (Ss - 1);
    const float* t = kvc + (size_t)row * KVC_D + KV_LR;
    float x1 = t[dd], x2 = t[dd + 32];
    float c = g_cos[s * 32 + dd], sn = g_sin[s * 32 + dd];
    float val = (d < 32) ? (x1 * c - x2 * sn) : (x2 * c + x1 * sn);
#pragma unroll
    for (int h = 0; h < NH; ++h)
        out[(((size_t)(b * NH + h) * Ss + s) * OUT_D) + 320 + d] = val;
}

// ---------------------------------------------------------------------------
// fp32 -> fp16 conversion pass
// ---------------------------------------------------------------------------
__global__ void __launch_bounds__(256) to_half_kernel(
    const float4* __restrict__ in, uint2* __restrict__ out, int n4)
{
    int i = blockIdx.x * blockDim.x + threadIdx.x;
    if (i < n4) {
        float4 v = in[i];
        __half2 h0 = __floats2half2_rn(v.x, v.y);
        __half2 h1 = __floats2half2_rn(v.z, v.w);
        out[i] = make_uint2(*(uint32_t*)&h0, *(uint32_t*)&h1);
    }
}

// ---------------------------------------------------------------------------
// LayerNorm: fp32 input, half output
// ---------------------------------------------------------------------------
__global__ void __launch_bounds__(256) ln_half_kernel(
    const float* __restrict__ X, int ld_in, int D,
    const float* __restrict__ gamma, const float* __restrict__ beta,
    __half* __restrict__ Y, int ld_out)
{
    const float* x = X + (size_t)blockIdx.x * ld_in;
    __half* y = Y + (size_t)blockIdx.x * ld_out;
    float s = 0.f, s2 = 0.f;
    for (int i = threadIdx.x; i < D; i += 256) {
        float v = x[i];
        s += v; s2 += v * v;
    }
    __shared__ float shs[8], shs2[8];
#pragma unroll
    for (int o = 16; o > 0; o >>= 1) {
        s  += __shfl_down_sync(0xffffffffu, s,  o);
        s2 += __shfl_down_sync(0xffffffffu, s2, o);
    }
    int w = threadIdx.x >> 5, l = threadIdx.x & 31;
    if (l == 0) { shs[w] = s; shs2[w] = s2; }
    __syncthreads();
    if (w == 0) {
        s  = (l < 8) ? shs[l]  : 0.f;
        s2 = (l < 8) ? shs2[l] : 0.f;
#pragma unroll
        for (int o = 4; o > 0; o >>= 1) {
            s  += __shfl_down_sync(0xffffffffu, s,  o);
            s2 += __shfl_down_sync(0xffffffffu, s2, o);
        }
        if (l == 0) { shs[0] = s; shs2[0] = s2; }
    }
    __syncthreads();
    float mu  = shs[0] / D;
    float var = shs2[0] / D - mu * mu;
    float inv = rsqrtf(var + 1e-5f);
    for (int i = threadIdx.x; i < D; i += 256)
        y[i] = __float2half_rn((x[i] - mu) * inv * gamma[i] + beta[i]);
}

// ---------------------------------------------------------------------------
// Launch
// ---------------------------------------------------------------------------
extern "C" void kernel_launch(void* const* d_in, const int* /*in_sizes*/, int /*n_in*/,
                              void* d_out, int /*out_size*/)
{
    const float* hidden   = (const float*)d_in[0];
    const float* w_qa     = (const float*)d_in[1];
    const float* b_qa     = (const float*)d_in[2];
    const float* g_qa_ln  = (const float*)d_in[3];
    const float* b_qa_ln  = (const float*)d_in[4];
    const float* w_qb     = (const float*)d_in[5];
    const float* b_qb     = (const float*)d_in[6];
    const float* w_kva    = (const float*)d_in[7];
    const float* b_kva    = (const float*)d_in[8];
    const float* g_kva_ln = (const float*)d_in[9];
    const float* b_kva_ln = (const float*)d_in[10];
    const float* w_kvb    = (const float*)d_in[11];
    const float* b_kvb    = (const float*)d_in[12];
    float* out = (float*)d_out;

    float  *qc, *kvc;
    __half *qch, *kvch, *hidh, *wqah, *wqbh, *wkvah, *wkvbh;
    cudaGetSymbolAddress((void**)&qc,    g_qc);
    cudaGetSymbolAddress((void**)&kvc,   g_kvc);
    cudaGetSymbolAddress((void**)&qch,   g_qch);
    cudaGetSymbolAddress((void**)&kvch,  g_kvch);
    cudaGetSymbolAddress((void**)&hidh,  g_hidh);
    cudaGetSymbolAddress((void**)&wqah,  g_wqah);
    cudaGetSymbolAddress((void**)&wqbh,  g_wqbh);
    cudaGetSymbolAddress((void**)&wkvah, g_wkvah);
    cudaGetSymbolAddress((void**)&wkvbh, g_wkvbh);

    cudaFuncSetAttribute(gemm_mma_f16_epi,
                         cudaFuncAttributeMaxDynamicSharedMemorySize, GEMM_SMEM);

    auto toHalf = [&](const float* src, __half* dst, int n) {
        int n4 = n / 4;
        to_half_kernel<<<(n4 + 255) / 256, 256>>>(
            (const float4*)src, (uint2*)dst, n4);
    };

    rope_table_kernel<<<(Ss * 32 + 255) / 256, 256>>>();

    toHalf(hidden, hidh,  Mrows * HID);
    toHalf(w_qa,   wqah,  Q_LR * HID);
    toHalf(w_qb,   wqbh,  QD * Q_LR);
    toHalf(w_kva,  wkvah, KVC_D * HID);
    toHalf(w_kvb,  wkvbh, KVD * KV_LR);

    const int mb = Mrows / BM;   // 64

    // q_c = hidden @ w_qa^T + b_qa   (8192 x 768, K=2048)
    gemm_mma_f16_epi<<<dim3((Q_LR + BN - 1) / BN, mb), 256, GEMM_SMEM>>>(
        hidh, HID, wqah, HID, b_qa, qc, Q_LR, Q_LR, HID, EPI_PLAIN);

    ln_half_kernel<<<Mrows, 256>>>(qc, Q_LR, Q_LR, g_qa_ln, b_qa_ln, qch, Q_LR);

    // kv_c = hidden @ w_kva^T + b_kva   (8192 x 576, K=2048)
    gemm_mma_f16_epi<<<dim3((KVC_D + BN - 1) / BN, mb), 256, GEMM_SMEM>>>(
        hidh, HID, wkvah, HID, b_kva, kvc, KVC_D, KVC_D, HID, EPI_PLAIN);

    // k_rope broadcast (pre-LN tail, untouched by LN)
    krope_kernel<<<Mrows / 4, 256>>>(kvc, out);

    ln_half_kernel<<<Mrows, 256>>>(kvc, KVC_D, KV_LR, g_kva_ln, b_kva_ln,
                                   kvch, KV_LR);

    // q = LN(q_c) @ w_qb^T + b_qb -> fused RoPE + scatter
    gemm_mma_f16_epi<<<dim3(QD / BN, mb), 256, GEMM_SMEM>>>(
        qch, Q_LR, wqbh, Q_LR, b_qb, out, OUT_D, QD, Q_LR, EPI_Q);

    // kv = LN(kv_c) @ w_kvb^T + b_kvb -> fused scatter
    gemm_mma_f16_epi<<<dim3(KVD / BN, mb), 256, GEMM_SMEM>>>(
        kvch, KV_LR, wkvbh, KV_LR, b_kvb, out, OUT_D, KVD, KV_LR, EPI_KV);
}

// round 9
// speedup vs baseline: 7.9613x; 1.3746x over previous
#include <cuda_runtime.h>
#include <cuda_fp16.h>
#include <cstdint>
#include <math.h>

// ---------------------------------------------------------------------------
// Problem constants
// ---------------------------------------------------------------------------
namespace {
constexpr int HID     = 2048;
constexpr int QK_NOPE = 128;
constexpr int QK_ROPE = 64;
constexpr int QK_HEAD = QK_NOPE + QK_ROPE;        // 192
constexpr int Q_LR    = 768;
constexpr int KV_LR   = 512;
constexpr int NH      = 16;
constexpr int V_DIM   = 128;
constexpr int Bb      = 2;
constexpr int Ss      = 4096;
constexpr int Mrows   = Bb * Ss;                  // 8192
constexpr int QD      = NH * QK_HEAD;             // 3072
constexpr int KVD     = NH * (QK_NOPE + V_DIM);   // 4096
constexpr int KVC_D   = KV_LR + QK_ROPE;          // 576
constexpr int OUT_D   = 512;
}

// ---------------------------------------------------------------------------
// Device scratch
// ---------------------------------------------------------------------------
__device__ float  g_qc  [Mrows * Q_LR];
__device__ float  g_kvc [Mrows * KVC_D];
__device__ __half g_qch [Mrows * Q_LR];
__device__ __half g_kvch[Mrows * KV_LR];
__device__ __half g_hidh[Mrows * HID];
__device__ __half g_wqah [Q_LR * HID];
__device__ __half g_wqbh [QD * Q_LR];
__device__ __half g_wkvah[KVC_D * HID];
__device__ __half g_wkvbh[KVD * KV_LR];
__device__ float  g_cos [Ss * 32];
__device__ float  g_sin [Ss * 32];

// ---------------------------------------------------------------------------
// Helpers
// ---------------------------------------------------------------------------
__device__ __forceinline__ uint32_t smem_u32(const void* p) {
    uint32_t a;
    asm("{ .reg .u64 t; cvta.to.shared.u64 t, %1; cvt.u32.u64 %0, t; }"
        : "=r"(a) : "l"(p));
    return a;
}

__device__ __forceinline__ void cp_async16(uint32_t dst, const void* src, bool valid) {
    int sz = valid ? 16 : 0;
    asm volatile("cp.async.ca.shared.global [%0], [%1], 16, %2;"
                 :: "r"(dst), "l"(src), "r"(sz) : "memory");
}
__device__ __forceinline__ void cp_commit() {
    asm volatile("cp.async.commit_group;" ::: "memory");
}
template <int N>
__device__ __forceinline__ void cp_wait() {
    asm volatile("cp.async.wait_group %0;" :: "n"(N) : "memory");
}

__device__ __forceinline__ void ldsm4(uint32_t& r0, uint32_t& r1,
                                      uint32_t& r2, uint32_t& r3, uint32_t addr) {
    asm volatile("ldmatrix.sync.aligned.m8n8.x4.shared.b16 {%0,%1,%2,%3}, [%4];"
                 : "=r"(r0), "=r"(r1), "=r"(r2), "=r"(r3) : "r"(addr));
}

__device__ __forceinline__ void mma16(float* c,
                                      uint32_t a0, uint32_t a1, uint32_t a2, uint32_t a3,
                                      uint32_t b0, uint32_t b1) {
    asm volatile(
        "mma.sync.aligned.m16n8k16.row.col.f32.f16.f16.f32 "
        "{%0,%1,%2,%3}, {%4,%5,%6,%7}, {%8,%9}, {%0,%1,%2,%3};"
        : "+f"(c[0]), "+f"(c[1]), "+f"(c[2]), "+f"(c[3])
        : "r"(a0), "r"(a1), "r"(a2), "r"(a3), "r"(b0), "r"(b1));
}

// ---------------------------------------------------------------------------
// GEMM config: block 128(M) x 128(N) x 32(K) halves, 256 threads, 8 warps
// (4M x 2N), warp tile 32x64, 3-stage cp.async, 2 CTAs/SM.
// ---------------------------------------------------------------------------
namespace {
constexpr int BM = 128;
constexpr int BN = 128;
constexpr int BK = 32;
constexpr int NSTAGE = 3;
constexpr int LDSH = 40;                              // halves/row incl pad
constexpr int A_ST_H = BM * LDSH;                     // 5120 halves
constexpr int B_ST_H = BN * LDSH;                     // 5120 halves
constexpr int STAGE_H = A_ST_H + B_ST_H;              // 10240 halves
constexpr uint32_t GEMM_SMEM = NSTAGE * STAGE_H * 2;  // 61440 B
}

enum { EPI_PLAIN = 0, EPI_Q = 1, EPI_KV = 2 };

struct GemmDesc {
    const __half* A;  int lda;
    const __half* B;  int ldb;
    const float*  bias;
    float*        C;  int ldc;
    int N, K, mode;
};

// Two GEMMs fused in one launch: blockIdx.x < split -> d0, else d1.
__global__ void __launch_bounds__(256, 2)
gemm_mma_f16_dual(GemmDesc d0, GemmDesc d1, int split)
{
    extern __shared__ __half smh[];
    const uint32_t sm_b = smem_u32(smh);

    const GemmDesc& D = (blockIdx.x < (unsigned)split) ? d0 : d1;
    const int bn = ((blockIdx.x < (unsigned)split) ? blockIdx.x
                                                   : (blockIdx.x - split)) * BN;
    const __half* __restrict__ A = D.A;
    const __half* __restrict__ B = D.B;
    const int lda = D.lda, ldb = D.ldb, N = D.N, K = D.K, MODE = D.mode;

    const int tid  = threadIdx.x;
    const int wid  = tid >> 5;
    const int lane = tid & 31;
    const int wm   = wid & 3;            // 4 M-warps
    const int wn   = wid >> 2;           // 2 N-warps
    const int bm   = blockIdx.y * BM;
    const int m0   = wm * 32;
    const int n0   = wn * 64;
    const int qr   = lane >> 2;
    const int qc   = lane & 3;

    const int aRow  = m0 + (lane & 15);
    const int aKoff = (lane >> 4) * 8;
    const int bRow  = n0 + ((lane >> 4) & 1) * 8 + (lane & 7);
    const int bKoff = ((lane >> 3) & 1) * 8;

    float acc[2][8][4];
#pragma unroll
    for (int i = 0; i < 2; i++)
#pragma unroll
        for (int j = 0; j < 8; j++)
#pragma unroll
            for (int k = 0; k < 4; k++) acc[i][j][k] = 0.f;

    const int T = K / BK;

    auto issue_stage = [&](int t) {
        const int buf = t % NSTAGE;
        const uint32_t aBase = sm_b + (uint32_t)buf * STAGE_H * 2;
        const uint32_t bBase = aBase + A_ST_H * 2;
        const int k0 = t * BK;
        // A: 128 rows x 32 halves = 512 x 16B, 2/thread
#pragma unroll
        for (int j = 0; j < 2; ++j) {
            int i = j * 256 + tid;
            int r = i >> 2, c8 = i & 3;
            cp_async16(aBase + (uint32_t)(r * LDSH * 2 + c8 * 16),
                       A + (size_t)(bm + r) * lda + k0 + c8 * 8, true);
        }
        // B: 128 rows x 32 halves, 2/thread (guard n<N)
#pragma unroll
        for (int j = 0; j < 2; ++j) {
            int i = j * 256 + tid;
            int r = i >> 2, c8 = i & 3;
            int n = bn + r;
            cp_async16(bBase + (uint32_t)(r * LDSH * 2 + c8 * 16),
                       B + (size_t)(n < N ? n : 0) * ldb + k0 + c8 * 8, n < N);
        }
        cp_commit();
    };

#pragma unroll
    for (int i = 0; i < NSTAGE - 1; ++i)
        if (i < T) issue_stage(i);

    for (int t = 0; t < T; ++t) {
        if (t < T - 1) cp_wait<NSTAGE - 2>(); else cp_wait<0>();
        __syncthreads();
        if (t + NSTAGE - 1 < T) issue_stage(t + NSTAGE - 1);

        const uint32_t As_u = sm_b + (uint32_t)(t % NSTAGE) * STAGE_H * 2;
        const uint32_t Bs_u = As_u + A_ST_H * 2;

#pragma unroll
        for (int kk = 0; kk < 2; ++kk) {
            const int kb = kk * 16;
            uint32_t a[2][4];
#pragma unroll
            for (int mf = 0; mf < 2; ++mf)
                ldsm4(a[mf][0], a[mf][1], a[mf][2], a[mf][3],
                      As_u + (uint32_t)((aRow + mf * 16) * LDSH + kb + aKoff) * 2);
            uint32_t b[8][2];
#pragma unroll
            for (int nfp = 0; nfp < 4; ++nfp)
                ldsm4(b[2 * nfp][0], b[2 * nfp][1], b[2 * nfp + 1][0], b[2 * nfp + 1][1],
                      Bs_u + (uint32_t)((bRow + nfp * 16) * LDSH + kb + bKoff) * 2);
#pragma unroll
            for (int nf = 0; nf < 8; ++nf)
#pragma unroll
                for (int mf = 0; mf < 2; ++mf)
                    mma16(acc[mf][nf], a[mf][0], a[mf][1], a[mf][2], a[mf][3],
                          b[nf][0], b[nf][1]);
        }
    }

    // -----------------------------------------------------------------------
    // Epilogues
    // -----------------------------------------------------------------------
    float* __restrict__ C = D.C;
    const float* __restrict__ bias = D.bias;
    const int ldc = D.ldc;

    if (MODE == EPI_PLAIN) {
#pragma unroll
        for (int nf = 0; nf < 8; ++nf) {
            int col = bn + n0 + nf * 8 + qc * 2;
            if (col >= N) continue;
            float2 bv = *(const float2*)(bias + col);
#pragma unroll
            for (int mf = 0; mf < 2; ++mf) {
                int r = bm + m0 + mf * 16 + qr;
                *(float2*)(C + (size_t)r * ldc + col) =
                    make_float2(acc[mf][nf][0] + bv.x, acc[mf][nf][1] + bv.y);
                *(float2*)(C + (size_t)(r + 8) * ldc + col) =
                    make_float2(acc[mf][nf][2] + bv.x, acc[mf][nf][3] + bv.y);
            }
        }
        return;
    }

    if (MODE == EPI_Q) {
        const int gn0  = bn + n0;           // multiple of 64
        const int h    = gn0 / QK_HEAD;
        const int w0   = gn0 % QK_HEAD;     // 0, 64, 128
        const bool rope = (w0 == 128);

        if (!rope) {
#pragma unroll
            for (int nf = 0; nf < 8; ++nf) {
                int col = gn0 + nf * 8 + qc * 2;
                float2 bv = *(const float2*)(bias + col);
                int oc = w0 + nf * 8 + qc * 2;
#pragma unroll
                for (int mf = 0; mf < 2; ++mf) {
#pragma unroll
                    for (int half = 0; half < 2; ++half) {
                        int r = bm + m0 + mf * 16 + qr + half * 8;
                        int b = r >> 12, s = r & (Ss - 1);
                        float* op = C + (((size_t)(b * NH + h) * Ss + s) * OUT_D) + oc;
                        *(float2*)op = make_float2(acc[mf][nf][half * 2]     + bv.x,
                                                   acc[mf][nf][half * 2 + 1] + bv.y);
                    }
                }
            }
        } else {
#pragma unroll
            for (int nf = 0; nf < 4; ++nf) {
                int d0  = nf * 8 + qc * 2;
                int col1 = gn0 + nf * 8 + qc * 2;
                int col2 = col1 + 32;
                float2 bv1 = *(const float2*)(bias + col1);
                float2 bv2 = *(const float2*)(bias + col2);
#pragma unroll
                for (int mf = 0; mf < 2; ++mf) {
#pragma unroll
                    for (int half = 0; half < 2; ++half) {
                        int r = bm + m0 + mf * 16 + qr + half * 8;
                        int b = r >> 12, s = r & (Ss - 1);
                        float ca = g_cos[s * 32 + d0],      sa = g_sin[s * 32 + d0];
                        float cbq = g_cos[s * 32 + d0 + 1], sbq = g_sin[s * 32 + d0 + 1];
                        float x1a = acc[mf][nf][half * 2]         + bv1.x;
                        float x1b = acc[mf][nf][half * 2 + 1]     + bv1.y;
                        float x2a = acc[mf][nf + 4][half * 2]     + bv2.x;
                        float x2b = acc[mf][nf + 4][half * 2 + 1] + bv2.y;
                        float* op = C + (((size_t)(b * NH + h) * Ss + s) * OUT_D);
                        *(float2*)(op + 128 + d0) =
                            make_float2(x1a * ca - x2a * sa, x1b * cbq - x2b * sbq);
                        *(float2*)(op + 160 + d0) =
                            make_float2(x2a * ca + x1a * sa, x2b * cbq + x1b * sbq);
                    }
                }
            }
        }
        return;
    }

    // MODE == EPI_KV
    {
#pragma unroll
        for (int nf = 0; nf < 8; ++nf) {
            int col = bn + n0 + nf * 8 + qc * 2;       // global col in 4096
            int h   = col >> 8;
            int cin = col & 255;
            float2 bv = *(const float2*)(bias + col);
            int oc = (cin < 128) ? (192 + cin) : (384 + (cin - 128));
#pragma unroll
            for (int mf = 0; mf < 2; ++mf) {
#pragma unroll
                for (int half = 0; half < 2; ++half) {
                    int r = bm + m0 + mf * 16 + qr + half * 8;
                    int b = r >> 12, s = r & (Ss - 1);
                    float* op = C + (((size_t)(b * NH + h) * Ss + s) * OUT_D) + oc;
                    *(float2*)op = make_float2(acc[mf][nf][half * 2]     + bv.x,
                                               acc[mf][nf][half * 2 + 1] + bv.y);
                }
            }
        }
    }
}

// ---------------------------------------------------------------------------
// RoPE cos/sin table
// ---------------------------------------------------------------------------
__global__ void __launch_bounds__(256) rope_table_kernel()
{
    int idx = blockIdx.x * 256 + threadIdx.x;
    if (idx >= Ss * 32) return;
    int dd = idx & 31;
    int s  = idx >> 5;
    float inv_freq = powf(10000.f, -(float)dd * (1.f / 32.f));
    float ang = (float)s * inv_freq;
    float sn, cs;
    sincosf(ang, &sn, &cs);
    g_cos[idx] = cs;
    g_sin[idx] = sn;
}

// ---------------------------------------------------------------------------
// k_rope broadcast
// ---------------------------------------------------------------------------
__global__ void __launch_bounds__(256) krope_kernel(
    const float* __restrict__ kvc, float* __restrict__ out)
{
    int row = blockIdx.x * 4 + (threadIdx.x >> 6);
    int d   = threadIdx.x & 63;
    int dd  = d & 31;
    int b   = row >> 12, s = row & (Ss - 1);
    const float* t = kvc + (size_t)row * KVC_D + KV_LR;
    float x1 = t[dd], x2 = t[dd + 32];
    float c = g_cos[s * 32 + dd], sn = g_sin[s * 32 + dd];
    float val = (d < 32) ? (x1 * c - x2 * sn) : (x2 * c + x1 * sn);
#pragma unroll
    for (int h = 0; h < NH; ++h)
        out[(((size_t)(b * NH + h) * Ss + s) * OUT_D) + 320 + d] = val;
}

// ---------------------------------------------------------------------------
// fp32 -> fp16 conversion pass
// ---------------------------------------------------------------------------
__global__ void __launch_bounds__(256) to_half_kernel(
    const float4* __restrict__ in, uint2* __restrict__ out, int n4)
{
    int i = blockIdx.x * blockDim.x + threadIdx.x;
    if (i < n4) {
        float4 v = in[i];
        __half2 h0 = __floats2half2_rn(v.x, v.y);
        __half2 h1 = __floats2half2_rn(v.z, v.w);
        out[i] = make_uint2(*(uint32_t*)&h0, *(uint32_t*)&h1);
    }
}

// ---------------------------------------------------------------------------
// LayerNorm: fp32 input, half output
// ---------------------------------------------------------------------------
__global__ void __launch_bounds__(256) ln_half_kernel(
    const float* __restrict__ X, int ld_in, int D,
    const float* __restrict__ gamma, const float* __restrict__ beta,
    __half* __restrict__ Y, int ld_out)
{
    const float* x = X + (size_t)blockIdx.x * ld_in;
    __half* y = Y + (size_t)blockIdx.x * ld_out;
    float s = 0.f, s2 = 0.f;
    for (int i = threadIdx.x; i < D; i += 256) {
        float v = x[i];
        s += v; s2 += v * v;
    }
    __shared__ float shs[8], shs2[8];
#pragma unroll
    for (int o = 16; o > 0; o >>= 1) {
        s  += __shfl_down_sync(0xffffffffu, s,  o);
        s2 += __shfl_down_sync(0xffffffffu, s2, o);
    }
    int w = threadIdx.x >> 5, l = threadIdx.x & 31;
    if (l == 0) { shs[w] = s; shs2[w] = s2; }
    __syncthreads();
    if (w == 0) {
        s  = (l < 8) ? shs[l]  : 0.f;
        s2 = (l < 8) ? shs2[l] : 0.f;
#pragma unroll
        for (int o = 4; o > 0; o >>= 1) {
            s  += __shfl_down_sync(0xffffffffu, s,  o);
            s2 += __shfl_down_sync(0xffffffffu, s2, o);
        }
        if (l == 0) { shs[0] = s; shs2[0] = s2; }
    }
    __syncthreads();
    float mu  = shs[0] / D;
    float var = shs2[0] / D - mu * mu;
    float inv = rsqrtf(var + 1e-5f);
    for (int i = threadIdx.x; i < D; i += 256)
        y[i] = __float2half_rn((x[i] - mu) * inv * gamma[i] + beta[i]);
}

// ---------------------------------------------------------------------------
// Launch
// ---------------------------------------------------------------------------
extern "C" void kernel_launch(void* const* d_in, const int* /*in_sizes*/, int /*n_in*/,
                              void* d_out, int /*out_size*/)
{
    const float* hidden   = (const float*)d_in[0];
    const float* w_qa     = (const float*)d_in[1];
    const float* b_qa     = (const float*)d_in[2];
    const float* g_qa_ln  = (const float*)d_in[3];
    const float* b_qa_ln  = (const float*)d_in[4];
    const float* w_qb     = (const float*)d_in[5];
    const float* b_qb     = (const float*)d_in[6];
    const float* w_kva    = (const float*)d_in[7];
    const float* b_kva    = (const float*)d_in[8];
    const float* g_kva_ln = (const float*)d_in[9];
    const float* b_kva_ln = (const float*)d_in[10];
    const float* w_kvb    = (const float*)d_in[11];
    const float* b_kvb    = (const float*)d_in[12];
    float* out = (float*)d_out;

    float  *qc, *kvc;
    __half *qch, *kvch, *hidh, *wqah, *wqbh, *wkvah, *wkvbh;
    cudaGetSymbolAddress((void**)&qc,    g_qc);
    cudaGetSymbolAddress((void**)&kvc,   g_kvc);
    cudaGetSymbolAddress((void**)&qch,   g_qch);
    cudaGetSymbolAddress((void**)&kvch,  g_kvch);
    cudaGetSymbolAddress((void**)&hidh,  g_hidh);
    cudaGetSymbolAddress((void**)&wqah,  g_wqah);
    cudaGetSymbolAddress((void**)&wqbh,  g_wqbh);
    cudaGetSymbolAddress((void**)&wkvah, g_wkvah);
    cudaGetSymbolAddress((void**)&wkvbh, g_wkvbh);

    cudaFuncSetAttribute(gemm_mma_f16_dual,
                         cudaFuncAttributeMaxDynamicSharedMemorySize, GEMM_SMEM);

    auto toHalf = [&](const float* src, __half* dst, int n) {
        int n4 = n / 4;
        to_half_kernel<<<(n4 + 255) / 256, 256>>>(
            (const float4*)src, (uint2*)dst, n4);
    };

    rope_table_kernel<<<(Ss * 32 + 255) / 256, 256>>>();

    toHalf(hidden, hidh,  Mrows * HID);
    toHalf(w_qa,   wqah,  Q_LR * HID);
    toHalf(w_qb,   wqbh,  QD * Q_LR);
    toHalf(w_kva,  wkvah, KVC_D * HID);
    toHalf(w_kvb,  wkvbh, KVD * KV_LR);

    const int mb = Mrows / BM;   // 64

    // --- fused G1 + G3: q_c and kv_c from hidden ---
    {
        GemmDesc d0{hidh, HID, wqah,  HID, b_qa,  qc,  Q_LR,  Q_LR,  HID, EPI_PLAIN};
        GemmDesc d1{hidh, HID, wkvah, HID, b_kva, kvc, KVC_D, KVC_D, HID, EPI_PLAIN};
        int nb0 = Q_LR / BN;                     // 6
        int nb1 = (KVC_D + BN - 1) / BN;         // 5
        gemm_mma_f16_dual<<<dim3(nb0 + nb1, mb), 256, GEMM_SMEM>>>(d0, d1, nb0);
    }

    ln_half_kernel<<<Mrows, 256>>>(qc, Q_LR, Q_LR, g_qa_ln, b_qa_ln, qch, Q_LR);
    krope_kernel<<<Mrows / 4, 256>>>(kvc, out);
    ln_half_kernel<<<Mrows, 256>>>(kvc, KVC_D, KV_LR, g_kva_ln, b_kva_ln,
                                   kvch, KV_LR);

    // --- fused G2 + G4: q (RoPE-fused) and kv (scatter-fused) into out ---
    {
        GemmDesc d0{qch,  Q_LR,  wqbh,  Q_LR,  b_qb,  out, OUT_D, QD,  Q_LR,  EPI_Q};
        GemmDesc d1{kvch, KV_LR, wkvbh, KV_LR, b_kvb, out, OUT_D, KVD, KV_LR, EPI_KV};
        int nb0 = QD / BN;                       // 24
        int nb1 = KVD / BN;                      // 32
        gemm_mma_f16_dual<<<dim3(nb0 + nb1, mb), 256, GEMM_SMEM>>>(d0, d1, nb0);
    }
}